// round 10
// baseline (speedup 1.0000x reference)
#include <cuda_runtime.h>
#include <cuda_bf16.h>
#include <math.h>
#include <stdint.h>

// ---------------------------------------------------------------------------
// Problem constants
// ---------------------------------------------------------------------------
#define B_SZ 4
#define T_SZ 64
#define N_SZ 128
#define D_DIM 1024
#define K2 2048
#define M_TOTAL 32768              // B*T*N
#define NEFF 3072                  // fused QKV output cols

// ---------------------------------------------------------------------------
// Scratch carve-out (single __device__ blob; allocation-free rule)
// ---------------------------------------------------------------------------
#define OFF_QKV  ((size_t)0)                        // fp32 [32768,3072]
#define OFF_A    (OFF_QKV + (size_t)402653184)      // fp32 [32768,2048] tf32
#define OFF_AOR  (OFF_A   + (size_t)268435456)      // fp32 [32768,1024] tf32
#define OFF_WT   (OFF_AOR + (size_t)134217728)      // fp32 [3072,2048]  tf32
#define OFF_WOT  (OFF_WT  + (size_t)25165824)       // fp32 [1024,1024]  tf32
#define SCRATCH_BYTES (OFF_WOT + (size_t)4194304)

__device__ __align__(1024) unsigned char g_scratch[SCRATCH_BYTES];

// ---------------------------------------------------------------------------
// PTX helpers (base sm_100 features only)
// ---------------------------------------------------------------------------
static __device__ __forceinline__ unsigned smem_u32(const void* p) {
    unsigned r;
    asm("{ .reg .u64 t; cvta.to.shared.u64 t, %1; cvt.u32.u64 %0, t; }"
        : "=r"(r) : "l"(p));
    return r;
}
static __device__ __forceinline__ void cp16(unsigned dst, const void* src) {
    asm volatile("cp.async.cg.shared.global [%0], [%1], 16;"
                 :: "r"(dst), "l"(src) : "memory");
}
static __device__ __forceinline__ void cp_commit() {
    asm volatile("cp.async.commit_group;" ::: "memory");
}
static __device__ __forceinline__ void cp_wait2() {
    asm volatile("cp.async.wait_group 2;" ::: "memory");
}
static __device__ __forceinline__ void ldmx4(
    unsigned& r0, unsigned& r1, unsigned& r2, unsigned& r3, unsigned addr) {
    asm volatile("ldmatrix.sync.aligned.m8n8.x4.shared.b16 {%0,%1,%2,%3}, [%4];"
                 : "=r"(r0), "=r"(r1), "=r"(r2), "=r"(r3) : "r"(addr));
}
static __device__ __forceinline__ void mma_tf32(
    float* c, const unsigned* a, unsigned b0, unsigned b1) {
    asm volatile(
        "mma.sync.aligned.m16n8k8.row.col.f32.tf32.tf32.f32 "
        "{%0,%1,%2,%3}, {%4,%5,%6,%7}, {%8,%9}, {%0,%1,%2,%3};"
        : "+f"(c[0]), "+f"(c[1]), "+f"(c[2]), "+f"(c[3])
        : "r"(a[0]), "r"(a[1]), "r"(a[2]), "r"(a[3]), "r"(b0), "r"(b1));
}
static __device__ __forceinline__ float tf32r(float x) {
    unsigned u;
    asm("cvt.rna.tf32.f32 %0, %1;" : "=r"(u) : "f"(x));
    return __uint_as_float(u);
}

// ---------------------------------------------------------------------------
// tf32 single-pass GEMM via mma.sync.m16n8k8.
// C[M, cstride-window] = relu( A @ WT^T + bias );
// CTA tile 128x128, BK=16, 8 warps (warptile 64x32), 4-stage cp.async,
// 2 CTAs/SM. Superchunk schedule: 2 chunks (64 MMAs) per sync pair, copies
// issued after the read-fence sync -> ~1 superchunk of LDG latency cover.
// ---------------------------------------------------------------------------
#define PK 20                          // floats per padded smem row (80B)
#define A_ST (128 * PK * 4)            // 10240 B
#define B_ST (128 * PK * 4)            // 10240 B
#define ST_BYTES (A_ST + B_ST)         // 20480 B
#define NSTG 4
#define GEMM_SMEM (NSTG * ST_BYTES)    // 81920 B per CTA

__global__ void __launch_bounds__(256, 2) mma_gemm(
    const float* __restrict__ A,
    const float* __restrict__ WT,
    const float* __restrict__ bias0,   // cols [0,1024)
    const float* __restrict__ bias1,   // cols [1024,2048)
    const float* __restrict__ bias2,   // cols [2048,3072)
    float* __restrict__ C,
    int K, int cstride)
{
    extern __shared__ __align__(16) unsigned char smem[];
    const unsigned sbase = smem_u32(smem);

    const int tid  = threadIdx.x;
    const int lane = tid & 31;
    const int warp = tid >> 5;
    const int wm   = warp >> 2;          // 0..1 (64-row slab)
    const int wn   = warp & 3;           // 0..3 (32-col slab)
    const int tileM = blockIdx.y * 128;
    const int tileN = blockIdx.x * 128;

    const int NC  = K >> 4;              // 16-wide K chunks (>= 64)
    const int NSC = NC >> 1;             // superchunks (2 chunks each)

    float acc[4][4][4];
    #pragma unroll
    for (int mi = 0; mi < 4; mi++)
        #pragma unroll
        for (int ni = 0; ni < 4; ni++)
            #pragma unroll
            for (int e = 0; e < 4; e++) acc[mi][ni][e] = 0.f;

    // copy chunk kc into stage s. A,B each 128x16 f32: 2 cp16/thread
    auto do_copy = [&](int kc, int s) {
        const int klocal = kc << 4;
        const unsigned stA = sbase + s * ST_BYTES;
        const unsigned stB = stA + A_ST;
        #pragma unroll
        for (int i = 0; i < 2; i++) {
            int idx = tid + i * 256;          // 0..511
            int r = idx >> 2, seg = idx & 3;  // 16B segment
            cp16(stA + (r * PK + seg * 4) * 4,
                 A + (size_t)(tileM + r) * K + klocal + seg * 4);
        }
        #pragma unroll
        for (int i = 0; i < 2; i++) {
            int idx = tid + i * 256;
            int r = idx >> 2, seg = idx & 3;
            cp16(stB + (r * PK + seg * 4) * 4,
                 WT + (size_t)(tileN + r) * K + klocal + seg * 4);
        }
    };

    // prologue: fill all 4 stages (chunks 0..3)
    #pragma unroll
    for (int p = 0; p < 4; p++) { do_copy(p, p); cp_commit(); }

    // per-lane ldmatrix row offsets (b16-tile trick: 8x8 b16 == 8x4 tf32)
    const int aRow = (lane & 7) + (lane & 8);          // m within 16
    const int aKof = (lane & 16) ? 4 : 0;              // k within 8
    const int bRow = (lane & 7) + ((lane & 16) ? 8 : 0);
    const int bKof = (lane & 8) ? 4 : 0;

    for (int sj = 0; sj < NSC; sj++) {
        cp_wait2();                 // chunks 2sj, 2sj+1 resident
        __syncthreads();            // visibility + all warps entered superchunk
        const int s0 = (sj << 1) & 3;

        #pragma unroll
        for (int c = 0; c < 2; c++) {
            const unsigned stA = sbase + (s0 + c) * ST_BYTES;
            const unsigned stB = stA + A_ST;
            #pragma unroll
            for (int ks = 0; ks < 2; ks++) {     // two k8 steps per chunk
                const int kb = ks * 8;
                unsigned a[4][4];
                #pragma unroll
                for (int mi = 0; mi < 4; mi++) {
                    int row = wm * 64 + mi * 16 + aRow;
                    ldmx4(a[mi][0], a[mi][1], a[mi][2], a[mi][3],
                          stA + (row * PK + kb + aKof) * 4);
                }
                unsigned b[4][2];
                #pragma unroll
                for (int ng = 0; ng < 2; ng++) {
                    int row = wn * 32 + ng * 16 + bRow;
                    unsigned r0, r1, r2, r3;
                    ldmx4(r0, r1, r2, r3, stB + (row * PK + kb + bKof) * 4);
                    b[ng * 2][0] = r0;      b[ng * 2][1] = r1;
                    b[ng * 2 + 1][0] = r2;  b[ng * 2 + 1][1] = r3;
                }
                #pragma unroll
                for (int mi = 0; mi < 4; mi++)
                    #pragma unroll
                    for (int ni = 0; ni < 4; ni++)
                        mma_tf32(acc[mi][ni], a[mi], b[ni][0], b[ni][1]);
            }
        }

        __syncthreads();            // all warps done reading stages s0, s0+1
        const int kc4 = (sj << 1) + 4;
        if (kc4 < NC)     { do_copy(kc4,     s0);     cp_commit(); }
        if (kc4 + 1 < NC) { do_copy(kc4 + 1, s0 + 1); cp_commit(); }
    }

    // epilogue: bias + relu
    #pragma unroll
    for (int mi = 0; mi < 4; mi++) {
        int r0 = tileM + wm * 64 + mi * 16 + (lane >> 2);
        #pragma unroll
        for (int ni = 0; ni < 4; ni++) {
            int c = tileN + wn * 32 + ni * 8 + 2 * (lane & 3);
            const float* bp = (c < 1024) ? bias0 : (c < 2048) ? bias1 : bias2;
            float b0 = bp[c & 1023], b1 = bp[(c + 1) & 1023];
            float2 v0, v1;
            v0.x = fmaxf(acc[mi][ni][0] + b0, 0.f);
            v0.y = fmaxf(acc[mi][ni][1] + b1, 0.f);
            v1.x = fmaxf(acc[mi][ni][2] + b0, 0.f);
            v1.y = fmaxf(acc[mi][ni][3] + b1, 0.f);
            *reinterpret_cast<float2*>(C + (size_t)r0 * cstride + c) = v0;
            *reinterpret_cast<float2*>(C + (size_t)(r0 + 8) * cstride + c) = v1;
        }
    }
}

// ---------------------------------------------------------------------------
// Prep kernels (tf32 rounding)
// ---------------------------------------------------------------------------
__global__ void __launch_bounds__(256) prep_a(
    const float* __restrict__ X, const float* __restrict__ STE,
    float* __restrict__ A)
{
    size_t idx = (size_t)blockIdx.x * 256 + threadIdx.x;   // one float4
    size_t row = idx >> 9;
    int    c4  = (int)(idx & 511) * 4;
    const float4 v = (c4 < 1024)
        ? *reinterpret_cast<const float4*>(X + row * 1024 + c4)
        : *reinterpret_cast<const float4*>(STE + row * 1024 + (c4 - 1024));
    float4 o;
    o.x = tf32r(v.x); o.y = tf32r(v.y); o.z = tf32r(v.z); o.w = tf32r(v.w);
    *reinterpret_cast<float4*>(A + row * 2048 + c4) = o;
}

// W [K,1024] -> WT [1024,K] tf32-rounded; blockIdx.z selects (Wq,Wk,Wv)
__global__ void __launch_bounds__(256) prep_wt_qkv(
    const float* __restrict__ W0, const float* __restrict__ W1,
    const float* __restrict__ W2, float* __restrict__ WT)
{
    __shared__ float t[32][33];
    const float* W = (blockIdx.z == 0) ? W0 : (blockIdx.z == 1) ? W1 : W2;
    float* O = WT + (size_t)blockIdx.z * 1024 * K2;
    const int kb = blockIdx.x * 32, nb = blockIdx.y * 32;
    const int x = threadIdx.x, y = threadIdx.y;
    #pragma unroll
    for (int i = 0; i < 32; i += 8)
        t[y + i][x] = W[(size_t)(kb + y + i) * 1024 + nb + x];
    __syncthreads();
    #pragma unroll
    for (int i = 0; i < 32; i += 8)
        O[(size_t)(nb + y + i) * K2 + kb + x] = tf32r(t[x][y + i]);
}

__global__ void __launch_bounds__(256) prep_wt_o(
    const float* __restrict__ W, float* __restrict__ WT)
{
    __shared__ float t[32][33];
    const int kb = blockIdx.x * 32, nb = blockIdx.y * 32;
    const int x = threadIdx.x, y = threadIdx.y;
    #pragma unroll
    for (int i = 0; i < 32; i += 8)
        t[y + i][x] = W[(size_t)(kb + y + i) * 1024 + nb + x];
    __syncthreads();
    #pragma unroll
    for (int i = 0; i < 32; i += 8)
        WT[(size_t)(nb + y + i) * D_DIM + kb + x] = tf32r(t[x][y + i]);
}

// ---------------------------------------------------------------------------
// Causal attention per (b, n, head); qkv fused [32768, 3072] fp32.
// Output written tf32-rounded (feeds the Wo GEMM directly).
// ---------------------------------------------------------------------------
__global__ void __launch_bounds__(128) attn_kernel(
    const float* __restrict__ QKV, float* __restrict__ O)
{
    __shared__ float qs[64][33];
    __shared__ float ks[64][33];
    __shared__ float vs[64][33];
    __shared__ float ps[64][65];

    const int bid = blockIdx.x;
    const int h = bid & 31;
    const int n = (bid >> 5) & 127;
    const int b = bid >> 12;
    const int tid = threadIdx.x;
    const int lane = tid & 31;
    const int warp = tid >> 5;

    const int hc = h * 32 + lane;

    #pragma unroll
    for (int i = 0; i < 16; i++) {
        int t = warp * 16 + i;
        size_t row = ((size_t)b * 64 + t) * 128 + n;
        const float* r = QKV + row * 3072;
        qs[t][lane] = r[hc];
        ks[t][lane] = r[1024 + hc];
        vs[t][lane] = r[2048 + hc];
    }
    __syncthreads();

    const float scale = 0.17677669529663687f;  // 1/sqrt(32)
    #pragma unroll 1
    for (int i = 0; i < 32; i++) {
        int idx = i * 128 + tid;
        int t = idx >> 6;
        int s = idx & 63;
        if (s <= t) {
            float acc = 0.f;
            #pragma unroll
            for (int kk = 0; kk < 32; kk++)
                acc = fmaf(qs[t][kk], ks[s][kk], acc);
            ps[t][s] = acc * scale;
        }
    }
    __syncthreads();

    #pragma unroll 1
    for (int i = 0; i < 16; i++) {
        int t = warp * 16 + i;
        float x0 = (lane <= t) ? ps[t][lane] : -1e30f;
        float x1 = (lane + 32 <= t) ? ps[t][lane + 32] : -1e30f;
        float m = fmaxf(x0, x1);
        #pragma unroll
        for (int o = 16; o; o >>= 1) m = fmaxf(m, __shfl_xor_sync(0xffffffffu, m, o));
        float e0 = (lane <= t) ? expf(x0 - m) : 0.f;
        float e1 = (lane + 32 <= t) ? expf(x1 - m) : 0.f;
        float sum = e0 + e1;
        #pragma unroll
        for (int o = 16; o; o >>= 1) sum += __shfl_xor_sync(0xffffffffu, sum, o);
        float inv = 1.f / sum;
        ps[t][lane] = e0 * inv;
        ps[t][lane + 32] = e1 * inv;
    }
    __syncthreads();

    #pragma unroll 1
    for (int i = 0; i < 16; i++) {
        int t = warp + 4 * i;
        float acc = 0.f;
        for (int s = 0; s <= t; s++)
            acc = fmaf(ps[t][s], vs[s][lane], acc);
        size_t row = ((size_t)b * 64 + t) * 128 + n;
        O[row * 1024 + hc] = tf32r(acc);
    }
}

// ---------------------------------------------------------------------------
extern "C" void kernel_launch(void* const* d_in, const int* in_sizes, int n_in,
                              void* d_out, int out_size)
{
    const float* X   = (const float*)d_in[0];
    const float* STE = (const float*)d_in[1];
    const float* Wq  = (const float*)d_in[2];
    const float* bq  = (const float*)d_in[3];
    const float* Wk  = (const float*)d_in[4];
    const float* bk  = (const float*)d_in[5];
    const float* Wv  = (const float*)d_in[6];
    const float* bv  = (const float*)d_in[7];
    const float* Wo  = (const float*)d_in[8];
    const float* bo  = (const float*)d_in[9];
    float* out = (float*)d_out;

    unsigned char* sc = nullptr;
    cudaGetSymbolAddress((void**)&sc, g_scratch);
    float* qkv = (float*)(sc + OFF_QKV);
    float* A   = (float*)(sc + OFF_A);
    float* AOR = (float*)(sc + OFF_AOR);
    float* WT  = (float*)(sc + OFF_WT);
    float* WOT = (float*)(sc + OFF_WOT);

    cudaFuncSetAttribute(mma_gemm,
                         cudaFuncAttributeMaxDynamicSharedMemorySize,
                         GEMM_SMEM);

    dim3 tb(32, 8);
    prep_a<<<65536, 256>>>(X, STE, A);                        // launch 0
    prep_wt_qkv<<<dim3(64, 32, 3), tb>>>(Wq, Wk, Wv, WT);     // launch 1
    prep_wt_o<<<dim3(32, 32), tb>>>(Wo, WOT);                 // launch 2

    // launch 3 (profiled): fused QKV projection
    mma_gemm<<<dim3(NEFF / 128, M_TOTAL / 128), 256, GEMM_SMEM>>>(
        A, WT, bq, bk, bv, qkv, K2, NEFF);

    // causal temporal attention (writes tf32-rounded output)
    attn_kernel<<<B_SZ * N_SZ * 32, 128>>>(qkv, AOR);

    // output projection
    mma_gemm<<<dim3(D_DIM / 128, M_TOTAL / 128), 256, GEMM_SMEM>>>(
        AOR, WOT, bo, bo, bo, out, D_DIM, D_DIM);
}

// round 11
// speedup vs baseline: 1.0854x; 1.0854x over previous
#include <cuda_runtime.h>
#include <cuda_bf16.h>
#include <math.h>
#include <stdint.h>

// ---------------------------------------------------------------------------
// Problem constants
// ---------------------------------------------------------------------------
#define B_SZ 4
#define T_SZ 64
#define N_SZ 128
#define D_DIM 1024
#define K2 2048
#define M_TOTAL 32768              // B*T*N
#define NEFF 3072                  // fused QKV output cols

// ---------------------------------------------------------------------------
// Scratch carve-out (single __device__ blob; allocation-free rule)
// ---------------------------------------------------------------------------
#define OFF_QKV  ((size_t)0)                        // fp32 [32768,3072]
#define OFF_A    (OFF_QKV + (size_t)402653184)      // fp32 [32768,2048] tf32
#define OFF_AOR  (OFF_A   + (size_t)268435456)      // fp32 [32768,1024] tf32
#define OFF_WT   (OFF_AOR + (size_t)134217728)      // fp32 [3072,2048]  tf32
#define OFF_WOT  (OFF_WT  + (size_t)25165824)       // fp32 [1024,1024]  tf32
#define SCRATCH_BYTES (OFF_WOT + (size_t)4194304)

__device__ __align__(1024) unsigned char g_scratch[SCRATCH_BYTES];

// ---------------------------------------------------------------------------
// PTX helpers (base sm_100 features only)
// ---------------------------------------------------------------------------
static __device__ __forceinline__ unsigned smem_u32(const void* p) {
    unsigned r;
    asm("{ .reg .u64 t; cvta.to.shared.u64 t, %1; cvt.u32.u64 %0, t; }"
        : "=r"(r) : "l"(p));
    return r;
}
static __device__ __forceinline__ void cp16(unsigned dst, const void* src) {
    asm volatile("cp.async.cg.shared.global [%0], [%1], 16;"
                 :: "r"(dst), "l"(src) : "memory");
}
static __device__ __forceinline__ void cp_commit() {
    asm volatile("cp.async.commit_group;" ::: "memory");
}
static __device__ __forceinline__ void cp_wait1() {
    asm volatile("cp.async.wait_group 1;" ::: "memory");
}
static __device__ __forceinline__ void bar_half(int id) {
    asm volatile("bar.sync %0, 128;" :: "r"(id) : "memory");
}
static __device__ __forceinline__ void ldmx4(
    unsigned& r0, unsigned& r1, unsigned& r2, unsigned& r3, unsigned addr) {
    asm volatile("ldmatrix.sync.aligned.m8n8.x4.shared.b16 {%0,%1,%2,%3}, [%4];"
                 : "=r"(r0), "=r"(r1), "=r"(r2), "=r"(r3) : "r"(addr));
}
static __device__ __forceinline__ void mma_tf32(
    float* c, const unsigned* a, unsigned b0, unsigned b1) {
    asm volatile(
        "mma.sync.aligned.m16n8k8.row.col.f32.tf32.tf32.f32 "
        "{%0,%1,%2,%3}, {%4,%5,%6,%7}, {%8,%9}, {%0,%1,%2,%3};"
        : "+f"(c[0]), "+f"(c[1]), "+f"(c[2]), "+f"(c[3])
        : "r"(a[0]), "r"(a[1]), "r"(a[2]), "r"(a[3]), "r"(b0), "r"(b1));
}
static __device__ __forceinline__ float tf32r(float x) {
    unsigned u;
    asm("cvt.rna.tf32.f32 %0, %1;" : "=r"(u) : "f"(x));
    return __uint_as_float(u);
}

// ---------------------------------------------------------------------------
// tf32 GEMM via mma.sync.m16n8k8, split-CTA independent halves.
// C[M, cstride-window] = relu( A @ WT^T + bias ).
// CTA tile 128x128; each half (4 warps, named barrier) owns 64 N-cols with a
// PRIVATE copy of the A tile + its B half -> no __syncthreads in mainloop;
// 4 independent sync domains per SM (2 CTAs x 2 halves) decorrelate barrier
// stalls. 3-stage cp.async, copy-early schedule (R9-style), 2 CTAs/SM.
// ---------------------------------------------------------------------------
#define PK 20                          // floats per padded smem row (80B)
#define A_HALF (128 * PK * 4)          // 10240 B (private A tile)
#define B_HALF (64 * PK * 4)           // 5120  B (private B half)
#define HALF_BYTES (A_HALF + B_HALF)   // 15360 B
#define ST_BYTES (2 * HALF_BYTES)      // 30720 B per stage
#define NSTG 3
#define GEMM_SMEM (NSTG * ST_BYTES)    // 92160 B per CTA

__global__ void __launch_bounds__(256, 2) mma_gemm(
    const float* __restrict__ A,
    const float* __restrict__ WT,
    const float* __restrict__ bias0,   // cols [0,1024)
    const float* __restrict__ bias1,   // cols [1024,2048)
    const float* __restrict__ bias2,   // cols [2048,3072)
    float* __restrict__ C,
    int K, int cstride)
{
    extern __shared__ __align__(16) unsigned char smem[];
    const unsigned sbase = smem_u32(smem);

    const int tid  = threadIdx.x;
    const int lane = tid & 31;
    const int warp = tid >> 5;
    const int half = warp >> 2;          // 0..1 (independent sync domain)
    const int w    = warp & 3;           // warp within half
    const int wm   = w >> 1;             // 0..1 (64-row slab)
    const int wn   = w & 1;              // 0..1 (32-col slab within 64)
    const int htid = tid & 127;          // thread within half
    const int tileM = blockIdx.y * 128;
    const int tileN = blockIdx.x * 128;
    const int colH  = tileN + half * 64; // this half's output col base

    const int NC = K >> 4;               // 16-wide K chunks

    float acc[4][4][4];
    #pragma unroll
    for (int mi = 0; mi < 4; mi++)
        #pragma unroll
        for (int ni = 0; ni < 4; ni++)
            #pragma unroll
            for (int e = 0; e < 4; e++) acc[mi][ni][e] = 0.f;

    // copy chunk kc into stage s (this half's private region).
    // A: 128x16 f32 (4 cp16/thread); B: 64x16 (2 cp16/thread)
    auto do_copy = [&](int kc, int s) {
        const int klocal = kc << 4;
        const unsigned base = sbase + s * ST_BYTES + half * HALF_BYTES;
        #pragma unroll
        for (int i = 0; i < 4; i++) {
            int idx = htid + i * 128;         // 0..511
            int r = idx >> 2, seg = idx & 3;  // 16B segment
            cp16(base + (r * PK + seg * 4) * 4,
                 A + (size_t)(tileM + r) * K + klocal + seg * 4);
        }
        #pragma unroll
        for (int i = 0; i < 2; i++) {
            int idx = htid + i * 128;         // 0..255
            int r = idx >> 2, seg = idx & 3;
            cp16(base + A_HALF + (r * PK + seg * 4) * 4,
                 WT + (size_t)(colH + r) * K + klocal + seg * 4);
        }
    };

    // prologue: fill stages 0,1
    do_copy(0, 0); cp_commit();
    do_copy(1, 1); cp_commit();

    // per-lane ldmatrix row offsets (b16-tile trick: 8x8 b16 == 8x4 tf32)
    const int aRow = (lane & 7) + (lane & 8);          // m within 16
    const int aKof = (lane & 16) ? 4 : 0;              // k within 8
    const int bRow = (lane & 7) + ((lane & 16) ? 8 : 0);
    const int bKof = (lane & 8) ? 4 : 0;

    int s = 0;                            // stage of chunk kc (kc % 3)
    for (int kc = 0; kc < NC; kc++) {
        cp_wait1();                       // chunk kc resident (1 outstanding)
        bar_half(half + 1);               // half's warps done with stage being reused
        // copy-early: next chunk goes into the stage read LAST iteration
        const int kn = kc + 2;
        int sn = s + 2; if (sn >= 3) sn -= 3;
        if (kn < NC) do_copy(kn, sn);
        cp_commit();                      // unconditional: keeps group accounting fixed

        const unsigned stA = sbase + s * ST_BYTES + half * HALF_BYTES;
        const unsigned stB = stA + A_HALF;
        #pragma unroll
        for (int ks = 0; ks < 2; ks++) {      // two k8 steps per chunk
            const int kb = ks * 8;
            unsigned a[4][4];
            #pragma unroll
            for (int mi = 0; mi < 4; mi++) {
                int row = wm * 64 + mi * 16 + aRow;
                ldmx4(a[mi][0], a[mi][1], a[mi][2], a[mi][3],
                      stA + (row * PK + kb + aKof) * 4);
            }
            unsigned b[4][2];
            #pragma unroll
            for (int ng = 0; ng < 2; ng++) {
                int row = wn * 32 + ng * 16 + bRow;
                unsigned r0, r1, r2, r3;
                ldmx4(r0, r1, r2, r3, stB + (row * PK + kb + bKof) * 4);
                b[ng * 2][0] = r0;      b[ng * 2][1] = r1;
                b[ng * 2 + 1][0] = r2;  b[ng * 2 + 1][1] = r3;
            }
            #pragma unroll
            for (int mi = 0; mi < 4; mi++)
                #pragma unroll
                for (int ni = 0; ni < 4; ni++)
                    mma_tf32(acc[mi][ni], a[mi], b[ni][0], b[ni][1]);
        }
        if (++s == 3) s = 0;
    }

    // epilogue: bias + relu (each warp writes its own tile; no sync needed)
    #pragma unroll
    for (int mi = 0; mi < 4; mi++) {
        int r0 = tileM + wm * 64 + mi * 16 + (lane >> 2);
        #pragma unroll
        for (int ni = 0; ni < 4; ni++) {
            int c = colH + wn * 32 + ni * 8 + 2 * (lane & 3);
            const float* bp = (c < 1024) ? bias0 : (c < 2048) ? bias1 : bias2;
            float b0 = bp[c & 1023], b1 = bp[(c + 1) & 1023];
            float2 v0, v1;
            v0.x = fmaxf(acc[mi][ni][0] + b0, 0.f);
            v0.y = fmaxf(acc[mi][ni][1] + b1, 0.f);
            v1.x = fmaxf(acc[mi][ni][2] + b0, 0.f);
            v1.y = fmaxf(acc[mi][ni][3] + b1, 0.f);
            *reinterpret_cast<float2*>(C + (size_t)r0 * cstride + c) = v0;
            *reinterpret_cast<float2*>(C + (size_t)(r0 + 8) * cstride + c) = v1;
        }
    }
}

// ---------------------------------------------------------------------------
// Prep kernels (tf32 rounding)
// ---------------------------------------------------------------------------
__global__ void __launch_bounds__(256) prep_a(
    const float* __restrict__ X, const float* __restrict__ STE,
    float* __restrict__ A)
{
    size_t idx = (size_t)blockIdx.x * 256 + threadIdx.x;   // one float4
    size_t row = idx >> 9;
    int    c4  = (int)(idx & 511) * 4;
    const float4 v = (c4 < 1024)
        ? *reinterpret_cast<const float4*>(X + row * 1024 + c4)
        : *reinterpret_cast<const float4*>(STE + row * 1024 + (c4 - 1024));
    float4 o;
    o.x = tf32r(v.x); o.y = tf32r(v.y); o.z = tf32r(v.z); o.w = tf32r(v.w);
    *reinterpret_cast<float4*>(A + row * 2048 + c4) = o;
}

// W [K,1024] -> WT [1024,K] tf32-rounded; blockIdx.z selects (Wq,Wk,Wv)
__global__ void __launch_bounds__(256) prep_wt_qkv(
    const float* __restrict__ W0, const float* __restrict__ W1,
    const float* __restrict__ W2, float* __restrict__ WT)
{
    __shared__ float t[32][33];
    const float* W = (blockIdx.z == 0) ? W0 : (blockIdx.z == 1) ? W1 : W2;
    float* O = WT + (size_t)blockIdx.z * 1024 * K2;
    const int kb = blockIdx.x * 32, nb = blockIdx.y * 32;
    const int x = threadIdx.x, y = threadIdx.y;
    #pragma unroll
    for (int i = 0; i < 32; i += 8)
        t[y + i][x] = W[(size_t)(kb + y + i) * 1024 + nb + x];
    __syncthreads();
    #pragma unroll
    for (int i = 0; i < 32; i += 8)
        O[(size_t)(nb + y + i) * K2 + kb + x] = tf32r(t[x][y + i]);
}

__global__ void __launch_bounds__(256) prep_wt_o(
    const float* __restrict__ W, float* __restrict__ WT)
{
    __shared__ float t[32][33];
    const int kb = blockIdx.x * 32, nb = blockIdx.y * 32;
    const int x = threadIdx.x, y = threadIdx.y;
    #pragma unroll
    for (int i = 0; i < 32; i += 8)
        t[y + i][x] = W[(size_t)(kb + y + i) * 1024 + nb + x];
    __syncthreads();
    #pragma unroll
    for (int i = 0; i < 32; i += 8)
        WT[(size_t)(nb + y + i) * D_DIM + kb + x] = tf32r(t[x][y + i]);
}

// ---------------------------------------------------------------------------
// Causal attention per (b, n, head); qkv fused [32768, 3072] fp32.
// Output written tf32-rounded (feeds the Wo GEMM directly).
// ---------------------------------------------------------------------------
__global__ void __launch_bounds__(128) attn_kernel(
    const float* __restrict__ QKV, float* __restrict__ O)
{
    __shared__ float qs[64][33];
    __shared__ float ks[64][33];
    __shared__ float vs[64][33];
    __shared__ float ps[64][65];

    const int bid = blockIdx.x;
    const int h = bid & 31;
    const int n = (bid >> 5) & 127;
    const int b = bid >> 12;
    const int tid = threadIdx.x;
    const int lane = tid & 31;
    const int warp = tid >> 5;

    const int hc = h * 32 + lane;

    #pragma unroll
    for (int i = 0; i < 16; i++) {
        int t = warp * 16 + i;
        size_t row = ((size_t)b * 64 + t) * 128 + n;
        const float* r = QKV + row * 3072;
        qs[t][lane] = r[hc];
        ks[t][lane] = r[1024 + hc];
        vs[t][lane] = r[2048 + hc];
    }
    __syncthreads();

    const float scale = 0.17677669529663687f;  // 1/sqrt(32)
    #pragma unroll 1
    for (int i = 0; i < 32; i++) {
        int idx = i * 128 + tid;
        int t = idx >> 6;
        int s = idx & 63;
        if (s <= t) {
            float acc = 0.f;
            #pragma unroll
            for (int kk = 0; kk < 32; kk++)
                acc = fmaf(qs[t][kk], ks[s][kk], acc);
            ps[t][s] = acc * scale;
        }
    }
    __syncthreads();

    #pragma unroll 1
    for (int i = 0; i < 16; i++) {
        int t = warp * 16 + i;
        float x0 = (lane <= t) ? ps[t][lane] : -1e30f;
        float x1 = (lane + 32 <= t) ? ps[t][lane + 32] : -1e30f;
        float m = fmaxf(x0, x1);
        #pragma unroll
        for (int o = 16; o; o >>= 1) m = fmaxf(m, __shfl_xor_sync(0xffffffffu, m, o));
        float e0 = (lane <= t) ? expf(x0 - m) : 0.f;
        float e1 = (lane + 32 <= t) ? expf(x1 - m) : 0.f;
        float sum = e0 + e1;
        #pragma unroll
        for (int o = 16; o; o >>= 1) sum += __shfl_xor_sync(0xffffffffu, sum, o);
        float inv = 1.f / sum;
        ps[t][lane] = e0 * inv;
        ps[t][lane + 32] = e1 * inv;
    }
    __syncthreads();

    #pragma unroll 1
    for (int i = 0; i < 16; i++) {
        int t = warp + 4 * i;
        float acc = 0.f;
        for (int s = 0; s <= t; s++)
            acc = fmaf(ps[t][s], vs[s][lane], acc);
        size_t row = ((size_t)b * 64 + t) * 128 + n;
        O[row * 1024 + hc] = tf32r(acc);
    }
}

// ---------------------------------------------------------------------------
extern "C" void kernel_launch(void* const* d_in, const int* in_sizes, int n_in,
                              void* d_out, int out_size)
{
    const float* X   = (const float*)d_in[0];
    const float* STE = (const float*)d_in[1];
    const float* Wq  = (const float*)d_in[2];
    const float* bq  = (const float*)d_in[3];
    const float* Wk  = (const float*)d_in[4];
    const float* bk  = (const float*)d_in[5];
    const float* Wv  = (const float*)d_in[6];
    const float* bv  = (const float*)d_in[7];
    const float* Wo  = (const float*)d_in[8];
    const float* bo  = (const float*)d_in[9];
    float* out = (float*)d_out;

    unsigned char* sc = nullptr;
    cudaGetSymbolAddress((void**)&sc, g_scratch);
    float* qkv = (float*)(sc + OFF_QKV);
    float* A   = (float*)(sc + OFF_A);
    float* AOR = (float*)(sc + OFF_AOR);
    float* WT  = (float*)(sc + OFF_WT);
    float* WOT = (float*)(sc + OFF_WOT);

    cudaFuncSetAttribute(mma_gemm,
                         cudaFuncAttributeMaxDynamicSharedMemorySize,
                         GEMM_SMEM);

    dim3 tb(32, 8);
    prep_a<<<65536, 256>>>(X, STE, A);                        // launch 0
    prep_wt_qkv<<<dim3(64, 32, 3), tb>>>(Wq, Wk, Wv, WT);     // launch 1
    prep_wt_o<<<dim3(32, 32), tb>>>(Wo, WOT);                 // launch 2

    // launch 3 (profiled): fused QKV projection
    mma_gemm<<<dim3(NEFF / 128, M_TOTAL / 128), 256, GEMM_SMEM>>>(
        A, WT, bq, bk, bv, qkv, K2, NEFF);

    // causal temporal attention (writes tf32-rounded output)
    attn_kernel<<<B_SZ * N_SZ * 32, 128>>>(qkv, AOR);

    // output projection
    mma_gemm<<<dim3(D_DIM / 128, M_TOTAL / 128), 256, GEMM_SMEM>>>(
        AOR, WOT, bo, bo, bo, out, D_DIM, D_DIM);
}

// round 12
// speedup vs baseline: 1.1916x; 1.0978x over previous
#include <cuda_runtime.h>
#include <cuda_bf16.h>
#include <math.h>
#include <stdint.h>

// ---------------------------------------------------------------------------
// Problem constants
// ---------------------------------------------------------------------------
#define B_SZ 4
#define T_SZ 64
#define N_SZ 128
#define D_DIM 1024
#define K2 2048
#define M_TOTAL 32768              // B*T*N
#define NEFF 3072                  // fused QKV output cols

// ---------------------------------------------------------------------------
// Scratch carve-out (single __device__ blob; allocation-free rule)
// ---------------------------------------------------------------------------
#define OFF_QKV  ((size_t)0)                        // fp32 [32768,3072]
#define OFF_A    (OFF_QKV + (size_t)402653184)      // fp32 [32768,2048] tf32
#define OFF_AOR  (OFF_A   + (size_t)268435456)      // fp32 [32768,1024] tf32
#define OFF_WT   (OFF_AOR + (size_t)134217728)      // fp32 [3072,2048]  tf32
#define OFF_WOT  (OFF_WT  + (size_t)25165824)       // fp32 [1024,1024]  tf32
#define SCRATCH_BYTES (OFF_WOT + (size_t)4194304)

__device__ __align__(1024) unsigned char g_scratch[SCRATCH_BYTES];

// ---------------------------------------------------------------------------
// PTX helpers (base sm_100 features only)
// ---------------------------------------------------------------------------
static __device__ __forceinline__ unsigned smem_u32(const void* p) {
    unsigned r;
    asm("{ .reg .u64 t; cvta.to.shared.u64 t, %1; cvt.u32.u64 %0, t; }"
        : "=r"(r) : "l"(p));
    return r;
}
static __device__ __forceinline__ void cp16(unsigned dst, const void* src) {
    asm volatile("cp.async.cg.shared.global [%0], [%1], 16;"
                 :: "r"(dst), "l"(src) : "memory");
}
static __device__ __forceinline__ void cp_commit() {
    asm volatile("cp.async.commit_group;" ::: "memory");
}
static __device__ __forceinline__ void cp_wait2() {
    asm volatile("cp.async.wait_group 2;" ::: "memory");
}
static __device__ __forceinline__ void ldmx4(
    unsigned& r0, unsigned& r1, unsigned& r2, unsigned& r3, unsigned addr) {
    asm volatile("ldmatrix.sync.aligned.m8n8.x4.shared.b16 {%0,%1,%2,%3}, [%4];"
                 : "=r"(r0), "=r"(r1), "=r"(r2), "=r"(r3) : "r"(addr));
}
static __device__ __forceinline__ void mma_tf32(
    float* c, const unsigned* a, unsigned b0, unsigned b1) {
    asm volatile(
        "mma.sync.aligned.m16n8k8.row.col.f32.tf32.tf32.f32 "
        "{%0,%1,%2,%3}, {%4,%5,%6,%7}, {%8,%9}, {%0,%1,%2,%3};"
        : "+f"(c[0]), "+f"(c[1]), "+f"(c[2]), "+f"(c[3])
        : "r"(a[0]), "r"(a[1]), "r"(a[2]), "r"(a[3]), "r"(b0), "r"(b1));
}
static __device__ __forceinline__ float tf32r(float x) {
    unsigned u;
    asm("cvt.rna.tf32.f32 %0, %1;" : "=r"(u) : "f"(x));
    return __uint_as_float(u);
}

// ---------------------------------------------------------------------------
// tf32 single-pass GEMM via mma.sync.m16n8k8  (R9 schedule — best measured).
// C[M, cstride-window] = relu( A @ WT^T + bias );
// CTA tile 128x128, BK=16, 8 warps (warptile 64x32), 4-stage cp.async,
// copy-early (issue next copy right after wait+sync), 2 CTAs/SM.
// ---------------------------------------------------------------------------
#define PK 20                          // floats per padded smem row (80B)
#define A_ST (128 * PK * 4)            // 10240 B
#define B_ST (128 * PK * 4)            // 10240 B
#define ST_BYTES (A_ST + B_ST)         // 20480 B
#define NSTG 4
#define GEMM_SMEM (NSTG * ST_BYTES)    // 81920 B per CTA

__global__ void __launch_bounds__(256, 2) mma_gemm(
    const float* __restrict__ A,
    const float* __restrict__ WT,
    const float* __restrict__ bias0,   // cols [0,1024)
    const float* __restrict__ bias1,   // cols [1024,2048)
    const float* __restrict__ bias2,   // cols [2048,3072)
    float* __restrict__ C,
    int K, int cstride)
{
    extern __shared__ __align__(16) unsigned char smem[];
    const unsigned sbase = smem_u32(smem);

    const int tid  = threadIdx.x;
    const int lane = tid & 31;
    const int warp = tid >> 5;
    const int wm   = warp >> 2;          // 0..1 (64-row slab)
    const int wn   = warp & 3;           // 0..3 (32-col slab)
    const int tileM = blockIdx.y * 128;
    const int tileN = blockIdx.x * 128;

    const int NC = K >> 4;               // 16-wide K chunks

    float acc[4][4][4];
    #pragma unroll
    for (int mi = 0; mi < 4; mi++)
        #pragma unroll
        for (int ni = 0; ni < 4; ni++)
            #pragma unroll
            for (int e = 0; e < 4; e++) acc[mi][ni][e] = 0.f;

    // copy chunk kc into stage s. A,B each 128x16 f32: 2 cp16/thread
    auto do_copy = [&](int kc, int s) {
        const int klocal = kc << 4;
        const unsigned stA = sbase + s * ST_BYTES;
        const unsigned stB = stA + A_ST;
        #pragma unroll
        for (int i = 0; i < 2; i++) {
            int idx = tid + i * 256;          // 0..511
            int r = idx >> 2, seg = idx & 3;  // 16B segment
            cp16(stA + (r * PK + seg * 4) * 4,
                 A + (size_t)(tileM + r) * K + klocal + seg * 4);
        }
        #pragma unroll
        for (int i = 0; i < 2; i++) {
            int idx = tid + i * 256;
            int r = idx >> 2, seg = idx & 3;
            cp16(stB + (r * PK + seg * 4) * 4,
                 WT + (size_t)(tileN + r) * K + klocal + seg * 4);
        }
    };

    #pragma unroll
    for (int p = 0; p < 3; p++) { do_copy(p, p); cp_commit(); }

    // per-lane ldmatrix row offsets (b16-tile trick: 8x8 b16 == 8x4 tf32)
    const int aRow = (lane & 7) + (lane & 8);          // m within 16
    const int aKof = (lane & 16) ? 4 : 0;              // k within 8
    const int bRow = (lane & 7) + ((lane & 16) ? 8 : 0);
    const int bKof = (lane & 8) ? 4 : 0;

    for (int kc = 0; kc < NC; kc++) {
        const int s = kc & (NSTG - 1);
        cp_wait2();                     // chunk kc resident
        __syncthreads();                // all warps done with stage being reused
        if (kc + 3 < NC) do_copy(kc + 3, (kc + 3) & (NSTG - 1));
        cp_commit();

        const unsigned stA = sbase + s * ST_BYTES;
        const unsigned stB = stA + A_ST;
        #pragma unroll
        for (int ks = 0; ks < 2; ks++) {     // two k8 steps per 16-chunk
            const int kb = ks * 8;
            unsigned a[4][4];
            #pragma unroll
            for (int mi = 0; mi < 4; mi++) {
                int row = wm * 64 + mi * 16 + aRow;
                ldmx4(a[mi][0], a[mi][1], a[mi][2], a[mi][3],
                      stA + (row * PK + kb + aKof) * 4);
            }
            unsigned b[4][2];
            #pragma unroll
            for (int ng = 0; ng < 2; ng++) {
                int row = wn * 32 + ng * 16 + bRow;
                unsigned r0, r1, r2, r3;
                ldmx4(r0, r1, r2, r3, stB + (row * PK + kb + bKof) * 4);
                b[ng * 2][0] = r0;      b[ng * 2][1] = r1;
                b[ng * 2 + 1][0] = r2;  b[ng * 2 + 1][1] = r3;
            }
            #pragma unroll
            for (int mi = 0; mi < 4; mi++)
                #pragma unroll
                for (int ni = 0; ni < 4; ni++)
                    mma_tf32(acc[mi][ni], a[mi], b[ni][0], b[ni][1]);
        }
    }

    // epilogue: bias + relu
    #pragma unroll
    for (int mi = 0; mi < 4; mi++) {
        int r0 = tileM + wm * 64 + mi * 16 + (lane >> 2);
        #pragma unroll
        for (int ni = 0; ni < 4; ni++) {
            int c = tileN + wn * 32 + ni * 8 + 2 * (lane & 3);
            const float* bp = (c < 1024) ? bias0 : (c < 2048) ? bias1 : bias2;
            float b0 = bp[c & 1023], b1 = bp[(c + 1) & 1023];
            float2 v0, v1;
            v0.x = fmaxf(acc[mi][ni][0] + b0, 0.f);
            v0.y = fmaxf(acc[mi][ni][1] + b1, 0.f);
            v1.x = fmaxf(acc[mi][ni][2] + b0, 0.f);
            v1.y = fmaxf(acc[mi][ni][3] + b1, 0.f);
            *reinterpret_cast<float2*>(C + (size_t)r0 * cstride + c) = v0;
            *reinterpret_cast<float2*>(C + (size_t)(r0 + 8) * cstride + c) = v1;
        }
    }
}

// ---------------------------------------------------------------------------
// Prep kernels (tf32 rounding)
// ---------------------------------------------------------------------------
__global__ void __launch_bounds__(256) prep_a(
    const float* __restrict__ X, const float* __restrict__ STE,
    float* __restrict__ A)
{
    size_t idx = (size_t)blockIdx.x * 256 + threadIdx.x;   // one float4
    size_t row = idx >> 9;
    int    c4  = (int)(idx & 511) * 4;
    const float4 v = (c4 < 1024)
        ? *reinterpret_cast<const float4*>(X + row * 1024 + c4)
        : *reinterpret_cast<const float4*>(STE + row * 1024 + (c4 - 1024));
    float4 o;
    o.x = tf32r(v.x); o.y = tf32r(v.y); o.z = tf32r(v.z); o.w = tf32r(v.w);
    *reinterpret_cast<float4*>(A + row * 2048 + c4) = o;
}

// W [K,1024] -> WT [1024,K] tf32-rounded; blockIdx.z selects (Wq,Wk,Wv)
__global__ void __launch_bounds__(256) prep_wt_qkv(
    const float* __restrict__ W0, const float* __restrict__ W1,
    const float* __restrict__ W2, float* __restrict__ WT)
{
    __shared__ float t[32][33];
    const float* W = (blockIdx.z == 0) ? W0 : (blockIdx.z == 1) ? W1 : W2;
    float* O = WT + (size_t)blockIdx.z * 1024 * K2;
    const int kb = blockIdx.x * 32, nb = blockIdx.y * 32;
    const int x = threadIdx.x, y = threadIdx.y;
    #pragma unroll
    for (int i = 0; i < 32; i += 8)
        t[y + i][x] = W[(size_t)(kb + y + i) * 1024 + nb + x];
    __syncthreads();
    #pragma unroll
    for (int i = 0; i < 32; i += 8)
        O[(size_t)(nb + y + i) * K2 + kb + x] = tf32r(t[x][y + i]);
}

__global__ void __launch_bounds__(256) prep_wt_o(
    const float* __restrict__ W, float* __restrict__ WT)
{
    __shared__ float t[32][33];
    const int kb = blockIdx.x * 32, nb = blockIdx.y * 32;
    const int x = threadIdx.x, y = threadIdx.y;
    #pragma unroll
    for (int i = 0; i < 32; i += 8)
        t[y + i][x] = W[(size_t)(kb + y + i) * 1024 + nb + x];
    __syncthreads();
    #pragma unroll
    for (int i = 0; i < 32; i += 8)
        WT[(size_t)(nb + y + i) * D_DIM + kb + x] = tf32r(t[x][y + i]);
}

// ---------------------------------------------------------------------------
// Causal attention per (b, n, head); qkv fused [32768, 3072] fp32.
// Optimized: 2x2 register-tiled scores with K rows held in registers,
// __expf softmax, 2-row-tiled AV. Output tf32-rounded (feeds Wo GEMM).
// ---------------------------------------------------------------------------
__global__ void __launch_bounds__(128) attn_kernel(
    const float* __restrict__ QKV, float* __restrict__ O)
{
    __shared__ float qs[64][33];
    __shared__ float ks[64][33];
    __shared__ float vs[64][33];
    __shared__ float ps[64][65];

    const int bid = blockIdx.x;
    const int h = bid & 31;
    const int n = (bid >> 5) & 127;
    const int b = bid >> 12;
    const int tid = threadIdx.x;
    const int lane = tid & 31;
    const int warp = tid >> 5;

    const int hc = h * 32 + lane;

    #pragma unroll
    for (int i = 0; i < 16; i++) {
        int t = warp * 16 + i;
        size_t row = ((size_t)b * 64 + t) * 128 + n;
        const float* r = QKV + row * 3072;
        qs[t][lane] = r[hc];
        ks[t][lane] = r[1024 + hc];
        vs[t][lane] = r[2048 + hc];
    }
    __syncthreads();

    // ---- scores: warp handles t-pairs (t0, t0+1), t0 = 2*warp + 8*j ----
    // each thread holds its two K rows (s = lane, lane+32) in registers
    float k0r[32], k1r[32];
    #pragma unroll
    for (int kk = 0; kk < 32; kk++) {
        k0r[kk] = ks[lane][kk];
        k1r[kk] = ks[lane + 32][kk];
    }
    const float scale = 0.17677669529663687f;  // 1/sqrt(32)
    #pragma unroll 1
    for (int j = 0; j < 8; j++) {
        const int t0 = 2 * warp + 8 * j;       // warp-uniform
        const int t1 = t0 + 1;
        float a00 = 0.f, a01 = 0.f, a10 = 0.f, a11 = 0.f;
        if (t1 >= 32) {                        // s in [32,64) partially live
            #pragma unroll
            for (int kk = 0; kk < 32; kk++) {
                float q0 = qs[t0][kk], q1 = qs[t1][kk];
                a00 = fmaf(q0, k0r[kk], a00);
                a01 = fmaf(q0, k1r[kk], a01);
                a10 = fmaf(q1, k0r[kk], a10);
                a11 = fmaf(q1, k1r[kk], a11);
            }
        } else {                               // upper s-half fully masked
            #pragma unroll
            for (int kk = 0; kk < 32; kk++) {
                float q0 = qs[t0][kk], q1 = qs[t1][kk];
                a00 = fmaf(q0, k0r[kk], a00);
                a10 = fmaf(q1, k0r[kk], a10);
            }
        }
        if (lane <= t0)      ps[t0][lane]      = a00 * scale;
        if (lane <= t1)      ps[t1][lane]      = a10 * scale;
        if (lane + 32 <= t0) ps[t0][lane + 32] = a01 * scale;
        if (lane + 32 <= t1) ps[t1][lane + 32] = a11 * scale;
    }
    __syncthreads();

    // ---- softmax per row (masked entries written as exact 0) ----
    #pragma unroll 1
    for (int i = 0; i < 16; i++) {
        int t = warp * 16 + i;
        float x0 = (lane <= t) ? ps[t][lane] : -1e30f;
        float x1 = (lane + 32 <= t) ? ps[t][lane + 32] : -1e30f;
        float m = fmaxf(x0, x1);
        #pragma unroll
        for (int o = 16; o; o >>= 1) m = fmaxf(m, __shfl_xor_sync(0xffffffffu, m, o));
        float e0 = (lane <= t) ? __expf(x0 - m) : 0.f;
        float e1 = (lane + 32 <= t) ? __expf(x1 - m) : 0.f;
        float sum = e0 + e1;
        #pragma unroll
        for (int o = 16; o; o >>= 1) sum += __shfl_xor_sync(0xffffffffu, sum, o);
        float inv = 1.f / sum;
        ps[t][lane] = e0 * inv;
        ps[t][lane + 32] = e1 * inv;
    }
    __syncthreads();

    // ---- AV: t-pairs share each vs load; ps upper triangle is exact 0 ----
    #pragma unroll 1
    for (int i = 0; i < 8; i++) {
        const int t0 = 2 * warp + 8 * i;
        const int t1 = t0 + 1;
        float acc0 = 0.f, acc1 = 0.f;
        for (int s = 0; s <= t1; s++) {
            float v = vs[s][lane];
            acc0 = fmaf(ps[t0][s], v, acc0);   // ps[t0][t1] == 0
            acc1 = fmaf(ps[t1][s], v, acc1);
        }
        size_t row0 = ((size_t)b * 64 + t0) * 128 + n;
        O[row0 * 1024 + hc] = tf32r(acc0);
        O[(row0 + 128) * 1024 + hc] = tf32r(acc1);
    }
}

// ---------------------------------------------------------------------------
extern "C" void kernel_launch(void* const* d_in, const int* in_sizes, int n_in,
                              void* d_out, int out_size)
{
    const float* X   = (const float*)d_in[0];
    const float* STE = (const float*)d_in[1];
    const float* Wq  = (const float*)d_in[2];
    const float* bq  = (const float*)d_in[3];
    const float* Wk  = (const float*)d_in[4];
    const float* bk  = (const float*)d_in[5];
    const float* Wv  = (const float*)d_in[6];
    const float* bv  = (const float*)d_in[7];
    const float* Wo  = (const float*)d_in[8];
    const float* bo  = (const float*)d_in[9];
    float* out = (float*)d_out;

    unsigned char* sc = nullptr;
    cudaGetSymbolAddress((void**)&sc, g_scratch);
    float* qkv = (float*)(sc + OFF_QKV);
    float* A   = (float*)(sc + OFF_A);
    float* AOR = (float*)(sc + OFF_AOR);
    float* WT  = (float*)(sc + OFF_WT);
    float* WOT = (float*)(sc + OFF_WOT);

    cudaFuncSetAttribute(mma_gemm,
                         cudaFuncAttributeMaxDynamicSharedMemorySize,
                         GEMM_SMEM);

    dim3 tb(32, 8);
    prep_a<<<65536, 256>>>(X, STE, A);                        // launch 0
    prep_wt_qkv<<<dim3(64, 32, 3), tb>>>(Wq, Wk, Wv, WT);     // launch 1
    prep_wt_o<<<dim3(32, 32), tb>>>(Wo, WOT);                 // launch 2

    // launch 3 (profiled): fused QKV projection
    mma_gemm<<<dim3(NEFF / 128, M_TOTAL / 128), 256, GEMM_SMEM>>>(
        A, WT, bq, bk, bv, qkv, K2, NEFF);

    // causal temporal attention (writes tf32-rounded output)
    attn_kernel<<<B_SZ * N_SZ * 32, 128>>>(qkv, AOR);

    // output projection
    mma_gemm<<<dim3(D_DIM / 128, M_TOTAL / 128), 256, GEMM_SMEM>>>(
        AOR, WOT, bo, bo, bo, out, D_DIM, D_DIM);
}

// round 13
// speedup vs baseline: 1.9088x; 1.6019x over previous
#include <cuda_runtime.h>
#include <cuda_fp16.h>
#include <math.h>
#include <stdint.h>

// ---------------------------------------------------------------------------
// Problem constants
// ---------------------------------------------------------------------------
#define B_SZ 4
#define T_SZ 64
#define N_SZ 128
#define D_DIM 1024
#define K2 2048
#define M_TOTAL 32768              // B*T*N
#define NEFF 3072                  // fused QKV output cols

// ---------------------------------------------------------------------------
// Scratch carve-out (single __device__ blob; allocation-free rule)
// ---------------------------------------------------------------------------
#define OFF_QKV  ((size_t)0)                        // fp32 [32768,3072]
#define OFF_A    (OFF_QKV + (size_t)402653184)      // fp16 [32768,2048]
#define OFF_AOR  (OFF_A   + (size_t)134217728)      // fp16 [32768,1024]
#define OFF_WT   (OFF_AOR + (size_t)67108864)       // fp16 [3072,2048]
#define OFF_WOT  (OFF_WT  + (size_t)12582912)       // fp16 [1024,1024]
#define SCRATCH_BYTES (OFF_WOT + (size_t)2097152)

__device__ __align__(1024) unsigned char g_scratch[SCRATCH_BYTES];

// ---------------------------------------------------------------------------
// PTX helpers (base sm_100 features only)
// ---------------------------------------------------------------------------
static __device__ __forceinline__ unsigned smem_u32(const void* p) {
    unsigned r;
    asm("{ .reg .u64 t; cvta.to.shared.u64 t, %1; cvt.u32.u64 %0, t; }"
        : "=r"(r) : "l"(p));
    return r;
}
static __device__ __forceinline__ void cp16(unsigned dst, const void* src) {
    asm volatile("cp.async.cg.shared.global [%0], [%1], 16;"
                 :: "r"(dst), "l"(src) : "memory");
}
static __device__ __forceinline__ void cp_commit() {
    asm volatile("cp.async.commit_group;" ::: "memory");
}
static __device__ __forceinline__ void cp_wait2() {
    asm volatile("cp.async.wait_group 2;" ::: "memory");
}
static __device__ __forceinline__ void ldmx4(
    unsigned& r0, unsigned& r1, unsigned& r2, unsigned& r3, unsigned addr) {
    asm volatile("ldmatrix.sync.aligned.m8n8.x4.shared.b16 {%0,%1,%2,%3}, [%4];"
                 : "=r"(r0), "=r"(r1), "=r"(r2), "=r"(r3) : "r"(addr));
}
static __device__ __forceinline__ void mma_f16(
    float* c, const unsigned* a, unsigned b0, unsigned b1) {
    asm volatile(
        "mma.sync.aligned.m16n8k16.row.col.f32.f16.f16.f32 "
        "{%0,%1,%2,%3}, {%4,%5,%6,%7}, {%8,%9}, {%0,%1,%2,%3};"
        : "+f"(c[0]), "+f"(c[1]), "+f"(c[2]), "+f"(c[3])
        : "r"(a[0]), "r"(a[1]), "r"(a[2]), "r"(a[3]), "r"(b0), "r"(b1));
}

// ---------------------------------------------------------------------------
// fp16 single-pass GEMM via mma.sync.m16n8k16 (2048 MACs/instr — 2x tf32).
// C[M, cstride-window] = relu( A @ WT^T + bias ); A,WT fp16, acc fp32.
// CTA tile 128x128, BK=32, 8 warps (warptile 64x32), 4-stage cp.async,
// copy-early schedule (R9 — best measured), 2 CTAs/SM.
// ---------------------------------------------------------------------------
#define PADK 40                        // halves per padded smem row (80B)
#define A_ST (128 * PADK * 2)          // 10240 B
#define B_ST (128 * PADK * 2)          // 10240 B
#define ST_BYTES (A_ST + B_ST)         // 20480 B
#define NSTG 4
#define GEMM_SMEM (NSTG * ST_BYTES)    // 81920 B per CTA

__global__ void __launch_bounds__(256, 2) mma_gemm(
    const __half* __restrict__ A,
    const __half* __restrict__ WT,
    const float* __restrict__ bias0,   // cols [0,1024)
    const float* __restrict__ bias1,   // cols [1024,2048)
    const float* __restrict__ bias2,   // cols [2048,3072)
    float* __restrict__ C,
    int K, int cstride)
{
    extern __shared__ __align__(16) unsigned char smem[];
    const unsigned sbase = smem_u32(smem);

    const int tid  = threadIdx.x;
    const int lane = tid & 31;
    const int warp = tid >> 5;
    const int wm   = warp >> 2;          // 0..1 (64-row slab)
    const int wn   = warp & 3;           // 0..3 (32-col slab)
    const int tileM = blockIdx.y * 128;
    const int tileN = blockIdx.x * 128;

    const int NC = K >> 5;               // 32-wide K chunks

    float acc[4][4][4];
    #pragma unroll
    for (int mi = 0; mi < 4; mi++)
        #pragma unroll
        for (int ni = 0; ni < 4; ni++)
            #pragma unroll
            for (int e = 0; e < 4; e++) acc[mi][ni][e] = 0.f;

    // copy chunk kc into stage s. A,B each 128x32 fp16 (64B/row): 2 cp16/thread
    auto do_copy = [&](int kc, int s) {
        const int klocal = kc << 5;
        const unsigned stA = sbase + s * ST_BYTES;
        const unsigned stB = stA + A_ST;
        #pragma unroll
        for (int i = 0; i < 2; i++) {
            int idx = tid + i * 256;          // 0..511
            int r = idx >> 2, c = idx & 3;    // c: 16B segment (8 halves)
            cp16(stA + (r * PADK + c * 8) * 2,
                 A + (size_t)(tileM + r) * K + klocal + c * 8);
        }
        #pragma unroll
        for (int i = 0; i < 2; i++) {
            int idx = tid + i * 256;
            int r = idx >> 2, c = idx & 3;
            cp16(stB + (r * PADK + c * 8) * 2,
                 WT + (size_t)(tileN + r) * K + klocal + c * 8);
        }
    };

    #pragma unroll
    for (int p = 0; p < 3; p++) { do_copy(p, p); cp_commit(); }

    for (int kc = 0; kc < NC; kc++) {
        const int s = kc & (NSTG - 1);
        cp_wait2();                     // chunk kc resident
        __syncthreads();                // all warps done with stage being reused
        if (kc + 3 < NC) do_copy(kc + 3, (kc + 3) & (NSTG - 1));
        cp_commit();

        const unsigned stA = sbase + s * ST_BYTES;
        const unsigned stB = stA + A_ST;
        #pragma unroll
        for (int ks = 0; ks < 2; ks++) {     // two k16 steps per 32-chunk
            unsigned a[4][4];
            #pragma unroll
            for (int mi = 0; mi < 4; mi++) {
                int row = wm * 64 + mi * 16 + (lane & 15);
                int kb  = ks * 16 + (lane >> 4) * 8;
                ldmx4(a[mi][0], a[mi][1], a[mi][2], a[mi][3],
                      stA + (row * PADK + kb) * 2);
            }
            unsigned b[4][2];
            #pragma unroll
            for (int ng = 0; ng < 2; ng++) {
                int row = wn * 32 + ng * 16 + ((lane >> 4) << 3) + (lane & 7);
                int kb  = ks * 16 + ((lane >> 3) & 1) * 8;
                unsigned r0, r1, r2, r3;
                ldmx4(r0, r1, r2, r3, stB + (row * PADK + kb) * 2);
                b[ng * 2][0] = r0;      b[ng * 2][1] = r1;
                b[ng * 2 + 1][0] = r2;  b[ng * 2 + 1][1] = r3;
            }
            #pragma unroll
            for (int mi = 0; mi < 4; mi++)
                #pragma unroll
                for (int ni = 0; ni < 4; ni++)
                    mma_f16(acc[mi][ni], a[mi], b[ni][0], b[ni][1]);
        }
    }

    // epilogue: bias + relu
    #pragma unroll
    for (int mi = 0; mi < 4; mi++) {
        int r0 = tileM + wm * 64 + mi * 16 + (lane >> 2);
        #pragma unroll
        for (int ni = 0; ni < 4; ni++) {
            int c = tileN + wn * 32 + ni * 8 + 2 * (lane & 3);
            const float* bp = (c < 1024) ? bias0 : (c < 2048) ? bias1 : bias2;
            float b0 = bp[c & 1023], b1 = bp[(c + 1) & 1023];
            float2 v0, v1;
            v0.x = fmaxf(acc[mi][ni][0] + b0, 0.f);
            v0.y = fmaxf(acc[mi][ni][1] + b1, 0.f);
            v1.x = fmaxf(acc[mi][ni][2] + b0, 0.f);
            v1.y = fmaxf(acc[mi][ni][3] + b1, 0.f);
            *reinterpret_cast<float2*>(C + (size_t)r0 * cstride + c) = v0;
            *reinterpret_cast<float2*>(C + (size_t)(r0 + 8) * cstride + c) = v1;
        }
    }
}

// ---------------------------------------------------------------------------
// Prep kernels (fp16 rna conversion)
// ---------------------------------------------------------------------------
__global__ void __launch_bounds__(256) prep_a(
    const float* __restrict__ X, const float* __restrict__ STE,
    __half* __restrict__ A)
{
    size_t idx = (size_t)blockIdx.x * 256 + threadIdx.x;   // one float4
    size_t row = idx >> 9;
    int    c4  = (int)(idx & 511) * 4;
    const float4 v = (c4 < 1024)
        ? *reinterpret_cast<const float4*>(X + row * 1024 + c4)
        : *reinterpret_cast<const float4*>(STE + row * 1024 + (c4 - 1024));
    ushort4 o;
    o.x = __half_as_ushort(__float2half_rn(v.x));
    o.y = __half_as_ushort(__float2half_rn(v.y));
    o.z = __half_as_ushort(__float2half_rn(v.z));
    o.w = __half_as_ushort(__float2half_rn(v.w));
    *reinterpret_cast<ushort4*>(A + row * 2048 + c4) = o;
}

// W [K,1024] -> WT [1024,K] fp16; blockIdx.z selects (Wq,Wk,Wv)
__global__ void __launch_bounds__(256) prep_wt_qkv(
    const float* __restrict__ W0, const float* __restrict__ W1,
    const float* __restrict__ W2, __half* __restrict__ WT)
{
    __shared__ float t[32][33];
    const float* W = (blockIdx.z == 0) ? W0 : (blockIdx.z == 1) ? W1 : W2;
    __half* O = WT + (size_t)blockIdx.z * 1024 * K2;
    const int kb = blockIdx.x * 32, nb = blockIdx.y * 32;
    const int x = threadIdx.x, y = threadIdx.y;
    #pragma unroll
    for (int i = 0; i < 32; i += 8)
        t[y + i][x] = W[(size_t)(kb + y + i) * 1024 + nb + x];
    __syncthreads();
    #pragma unroll
    for (int i = 0; i < 32; i += 8)
        O[(size_t)(nb + y + i) * K2 + kb + x] = __float2half_rn(t[x][y + i]);
}

__global__ void __launch_bounds__(256) prep_wt_o(
    const float* __restrict__ W, __half* __restrict__ WT)
{
    __shared__ float t[32][33];
    const int kb = blockIdx.x * 32, nb = blockIdx.y * 32;
    const int x = threadIdx.x, y = threadIdx.y;
    #pragma unroll
    for (int i = 0; i < 32; i += 8)
        t[y + i][x] = W[(size_t)(kb + y + i) * 1024 + nb + x];
    __syncthreads();
    #pragma unroll
    for (int i = 0; i < 32; i += 8)
        WT[(size_t)(nb + y + i) * D_DIM + kb + x] = __float2half_rn(t[x][y + i]);
}

// ---------------------------------------------------------------------------
// Causal attention per (b, n, head); qkv fused [32768, 3072] fp32.
// 2x2 register-tiled scores, __expf softmax, 2-row-tiled AV.
// Output written fp16 (feeds Wo GEMM directly).
// ---------------------------------------------------------------------------
__global__ void __launch_bounds__(128) attn_kernel(
    const float* __restrict__ QKV, __half* __restrict__ O)
{
    __shared__ float qs[64][33];
    __shared__ float ks[64][33];
    __shared__ float vs[64][33];
    __shared__ float ps[64][65];

    const int bid = blockIdx.x;
    const int h = bid & 31;
    const int n = (bid >> 5) & 127;
    const int b = bid >> 12;
    const int tid = threadIdx.x;
    const int lane = tid & 31;
    const int warp = tid >> 5;

    const int hc = h * 32 + lane;

    #pragma unroll
    for (int i = 0; i < 16; i++) {
        int t = warp * 16 + i;
        size_t row = ((size_t)b * 64 + t) * 128 + n;
        const float* r = QKV + row * 3072;
        qs[t][lane] = r[hc];
        ks[t][lane] = r[1024 + hc];
        vs[t][lane] = r[2048 + hc];
    }
    __syncthreads();

    // ---- scores: warp handles t-pairs (t0, t0+1); K rows in registers ----
    float k0r[32], k1r[32];
    #pragma unroll
    for (int kk = 0; kk < 32; kk++) {
        k0r[kk] = ks[lane][kk];
        k1r[kk] = ks[lane + 32][kk];
    }
    const float scale = 0.17677669529663687f;  // 1/sqrt(32)
    #pragma unroll 1
    for (int j = 0; j < 8; j++) {
        const int t0 = 2 * warp + 8 * j;       // warp-uniform
        const int t1 = t0 + 1;
        float a00 = 0.f, a01 = 0.f, a10 = 0.f, a11 = 0.f;
        if (t1 >= 32) {
            #pragma unroll
            for (int kk = 0; kk < 32; kk++) {
                float q0 = qs[t0][kk], q1 = qs[t1][kk];
                a00 = fmaf(q0, k0r[kk], a00);
                a01 = fmaf(q0, k1r[kk], a01);
                a10 = fmaf(q1, k0r[kk], a10);
                a11 = fmaf(q1, k1r[kk], a11);
            }
        } else {
            #pragma unroll
            for (int kk = 0; kk < 32; kk++) {
                float q0 = qs[t0][kk], q1 = qs[t1][kk];
                a00 = fmaf(q0, k0r[kk], a00);
                a10 = fmaf(q1, k0r[kk], a10);
            }
        }
        if (lane <= t0)      ps[t0][lane]      = a00 * scale;
        if (lane <= t1)      ps[t1][lane]      = a10 * scale;
        if (lane + 32 <= t0) ps[t0][lane + 32] = a01 * scale;
        if (lane + 32 <= t1) ps[t1][lane + 32] = a11 * scale;
    }
    __syncthreads();

    // ---- softmax per row (masked entries written as exact 0) ----
    #pragma unroll 1
    for (int i = 0; i < 16; i++) {
        int t = warp * 16 + i;
        float x0 = (lane <= t) ? ps[t][lane] : -1e30f;
        float x1 = (lane + 32 <= t) ? ps[t][lane + 32] : -1e30f;
        float m = fmaxf(x0, x1);
        #pragma unroll
        for (int o = 16; o; o >>= 1) m = fmaxf(m, __shfl_xor_sync(0xffffffffu, m, o));
        float e0 = (lane <= t) ? __expf(x0 - m) : 0.f;
        float e1 = (lane + 32 <= t) ? __expf(x1 - m) : 0.f;
        float sum = e0 + e1;
        #pragma unroll
        for (int o = 16; o; o >>= 1) sum += __shfl_xor_sync(0xffffffffu, sum, o);
        float inv = 1.f / sum;
        ps[t][lane] = e0 * inv;
        ps[t][lane + 32] = e1 * inv;
    }
    __syncthreads();

    // ---- AV: t-pairs share vs loads; upper-triangle ps entries are 0 ----
    #pragma unroll 1
    for (int i = 0; i < 8; i++) {
        const int t0 = 2 * warp + 8 * i;
        const int t1 = t0 + 1;
        float acc0 = 0.f, acc1 = 0.f;
        for (int s = 0; s <= t1; s++) {
            float v = vs[s][lane];
            acc0 = fmaf(ps[t0][s], v, acc0);   // ps[t0][t1] == 0
            acc1 = fmaf(ps[t1][s], v, acc1);
        }
        size_t row0 = ((size_t)b * 64 + t0) * 128 + n;
        O[row0 * 1024 + hc] = __float2half_rn(acc0);
        O[(row0 + 128) * 1024 + hc] = __float2half_rn(acc1);
    }
}

// ---------------------------------------------------------------------------
extern "C" void kernel_launch(void* const* d_in, const int* in_sizes, int n_in,
                              void* d_out, int out_size)
{
    const float* X   = (const float*)d_in[0];
    const float* STE = (const float*)d_in[1];
    const float* Wq  = (const float*)d_in[2];
    const float* bq  = (const float*)d_in[3];
    const float* Wk  = (const float*)d_in[4];
    const float* bk  = (const float*)d_in[5];
    const float* Wv  = (const float*)d_in[6];
    const float* bv  = (const float*)d_in[7];
    const float* Wo  = (const float*)d_in[8];
    const float* bo  = (const float*)d_in[9];
    float* out = (float*)d_out;

    unsigned char* sc = nullptr;
    cudaGetSymbolAddress((void**)&sc, g_scratch);
    float*  qkv = (float*)(sc + OFF_QKV);
    __half* A   = (__half*)(sc + OFF_A);
    __half* AOR = (__half*)(sc + OFF_AOR);
    __half* WT  = (__half*)(sc + OFF_WT);
    __half* WOT = (__half*)(sc + OFF_WOT);

    cudaFuncSetAttribute(mma_gemm,
                         cudaFuncAttributeMaxDynamicSharedMemorySize,
                         GEMM_SMEM);

    dim3 tb(32, 8);
    prep_a<<<65536, 256>>>(X, STE, A);                        // launch 0
    prep_wt_qkv<<<dim3(64, 32, 3), tb>>>(Wq, Wk, Wv, WT);     // launch 1
    prep_wt_o<<<dim3(32, 32), tb>>>(Wo, WOT);                 // launch 2

    // launch 3 (profiled): fused QKV projection
    mma_gemm<<<dim3(NEFF / 128, M_TOTAL / 128), 256, GEMM_SMEM>>>(
        A, WT, bq, bk, bv, qkv, K2, NEFF);

    // causal temporal attention (writes fp16 output)
    attn_kernel<<<B_SZ * N_SZ * 32, 128>>>(qkv, AOR);

    // output projection
    mma_gemm<<<dim3(D_DIM / 128, M_TOTAL / 128), 256, GEMM_SMEM>>>(
        AOR, WOT, bo, bo, bo, out, D_DIM, D_DIM);
}

// round 14
// speedup vs baseline: 2.0886x; 1.0942x over previous
#include <cuda_runtime.h>
#include <cuda_fp16.h>
#include <math.h>
#include <stdint.h>

// ---------------------------------------------------------------------------
// Problem constants
// ---------------------------------------------------------------------------
#define B_SZ 4
#define T_SZ 64
#define N_SZ 128
#define D_DIM 1024
#define K2 2048
#define M_TOTAL 32768              // B*T*N
#define NEFF 3072                  // fused QKV output cols

// ---------------------------------------------------------------------------
// Scratch carve-out (single __device__ blob; allocation-free rule)
// ---------------------------------------------------------------------------
#define OFF_QKV  ((size_t)0)                        // fp16 [32768,3072]
#define OFF_A    (OFF_QKV + (size_t)201326592)      // fp16 [32768,2048]
#define OFF_AOR  (OFF_A   + (size_t)134217728)      // fp16 [32768,1024]
#define OFF_WT   (OFF_AOR + (size_t)67108864)       // fp16 [3072,2048]
#define OFF_WOT  (OFF_WT  + (size_t)12582912)       // fp16 [1024,1024]
#define SCRATCH_BYTES (OFF_WOT + (size_t)2097152)

__device__ __align__(1024) unsigned char g_scratch[SCRATCH_BYTES];

// ---------------------------------------------------------------------------
// PTX helpers (base sm_100 features only)
// ---------------------------------------------------------------------------
static __device__ __forceinline__ unsigned smem_u32(const void* p) {
    unsigned r;
    asm("{ .reg .u64 t; cvta.to.shared.u64 t, %1; cvt.u32.u64 %0, t; }"
        : "=r"(r) : "l"(p));
    return r;
}
static __device__ __forceinline__ void cp16(unsigned dst, const void* src) {
    asm volatile("cp.async.cg.shared.global [%0], [%1], 16;"
                 :: "r"(dst), "l"(src) : "memory");
}
static __device__ __forceinline__ void cp_commit() {
    asm volatile("cp.async.commit_group;" ::: "memory");
}
static __device__ __forceinline__ void cp_wait1() {
    asm volatile("cp.async.wait_group 1;" ::: "memory");
}
static __device__ __forceinline__ void ldmx4(
    unsigned& r0, unsigned& r1, unsigned& r2, unsigned& r3, unsigned addr) {
    asm volatile("ldmatrix.sync.aligned.m8n8.x4.shared.b16 {%0,%1,%2,%3}, [%4];"
                 : "=r"(r0), "=r"(r1), "=r"(r2), "=r"(r3) : "r"(addr));
}
static __device__ __forceinline__ void mma_f16(
    float* c, const unsigned* a, unsigned b0, unsigned b1) {
    asm volatile(
        "mma.sync.aligned.m16n8k16.row.col.f32.f16.f16.f32 "
        "{%0,%1,%2,%3}, {%4,%5,%6,%7}, {%8,%9}, {%0,%1,%2,%3};"
        : "+f"(c[0]), "+f"(c[1]), "+f"(c[2]), "+f"(c[3])
        : "r"(a[0]), "r"(a[1]), "r"(a[2]), "r"(a[3]), "r"(b0), "r"(b1));
}

// ---------------------------------------------------------------------------
// fp16 GEMM via mma.sync.m16n8k16.
// C = relu( A @ WT^T + bias ); A,WT fp16, acc fp32; output fp16 or fp32.
// CTA tile 128x128, BK=64 (halved boundary count vs BK=32), 8 warps
// (warptile 64x32), 3-stage cp.async, copy-early schedule, 2 CTAs/SM.
// ---------------------------------------------------------------------------
#define PADK 72                        // halves per padded smem row (144B)
#define A_ST (128 * PADK * 2)          // 18432 B
#define B_ST (128 * PADK * 2)          // 18432 B
#define ST_BYTES (A_ST + B_ST)         // 36864 B
#define NSTG 3
#define GEMM_SMEM (NSTG * ST_BYTES)    // 110592 B per CTA

template <int HALF_OUT>
__global__ void __launch_bounds__(256, 2) mma_gemm(
    const __half* __restrict__ A,
    const __half* __restrict__ WT,
    const float* __restrict__ bias0,   // cols [0,1024)
    const float* __restrict__ bias1,   // cols [1024,2048)
    const float* __restrict__ bias2,   // cols [2048,3072)
    void* __restrict__ Cv,
    int K, int cstride)
{
    extern __shared__ __align__(16) unsigned char smem[];
    const unsigned sbase = smem_u32(smem);

    const int tid  = threadIdx.x;
    const int lane = tid & 31;
    const int warp = tid >> 5;
    const int wm   = warp >> 2;          // 0..1 (64-row slab)
    const int wn   = warp & 3;           // 0..3 (32-col slab)
    const int tileM = blockIdx.y * 128;
    const int tileN = blockIdx.x * 128;

    const int NC = K >> 6;               // 64-wide K chunks

    float acc[4][4][4];
    #pragma unroll
    for (int mi = 0; mi < 4; mi++)
        #pragma unroll
        for (int ni = 0; ni < 4; ni++)
            #pragma unroll
            for (int e = 0; e < 4; e++) acc[mi][ni][e] = 0.f;

    // copy chunk kc into stage s. A,B each 128x64 fp16 (128B/row): 4 cp16/thread
    auto do_copy = [&](int kc, int s) {
        const int klocal = kc << 6;
        const unsigned stA = sbase + s * ST_BYTES;
        const unsigned stB = stA + A_ST;
        #pragma unroll
        for (int i = 0; i < 4; i++) {
            int idx = tid + i * 256;          // 0..1023
            int r = idx >> 3, c = idx & 7;    // c: 16B segment (8 halves)
            cp16(stA + r * (PADK * 2) + c * 16,
                 A + (size_t)(tileM + r) * K + klocal + c * 8);
        }
        #pragma unroll
        for (int i = 0; i < 4; i++) {
            int idx = tid + i * 256;
            int r = idx >> 3, c = idx & 7;
            cp16(stB + r * (PADK * 2) + c * 16,
                 WT + (size_t)(tileN + r) * K + klocal + c * 8);
        }
    };

    // prologue: fill stages 0,1 (chunks 0,1)
    do_copy(0, 0); cp_commit();
    do_copy(1, 1); cp_commit();

    for (int kc = 0; kc < NC; kc++) {
        const int s = kc % 3;
        cp_wait1();                     // chunk kc resident (<=1 group pending)
        __syncthreads();                // all warps done reading stage (kc+2)%3
        {                               // copy-early: next chunk in flight now
            const int kn = kc + 2;
            if (kn < NC) do_copy(kn, kn % 3);
            cp_commit();
        }

        const unsigned stA = sbase + s * ST_BYTES;
        const unsigned stB = stA + A_ST;
        #pragma unroll
        for (int ks = 0; ks < 4; ks++) {     // four k16 steps per 64-chunk
            unsigned a[4][4];
            #pragma unroll
            for (int mi = 0; mi < 4; mi++) {
                int row = wm * 64 + mi * 16 + (lane & 15);
                int kb  = ks * 16 + (lane >> 4) * 8;
                ldmx4(a[mi][0], a[mi][1], a[mi][2], a[mi][3],
                      stA + row * (PADK * 2) + kb * 2);
            }
            unsigned b[4][2];
            #pragma unroll
            for (int ng = 0; ng < 2; ng++) {
                int row = wn * 32 + ng * 16 + ((lane >> 4) << 3) + (lane & 7);
                int kb  = ks * 16 + ((lane >> 3) & 1) * 8;
                unsigned r0, r1, r2, r3;
                ldmx4(r0, r1, r2, r3, stB + row * (PADK * 2) + kb * 2);
                b[ng * 2][0] = r0;      b[ng * 2][1] = r1;
                b[ng * 2 + 1][0] = r2;  b[ng * 2 + 1][1] = r3;
            }
            #pragma unroll
            for (int mi = 0; mi < 4; mi++)
                #pragma unroll
                for (int ni = 0; ni < 4; ni++)
                    mma_f16(acc[mi][ni], a[mi], b[ni][0], b[ni][1]);
        }
    }

    // epilogue: bias + relu; fp16 or fp32 output
    #pragma unroll
    for (int mi = 0; mi < 4; mi++) {
        int r0 = tileM + wm * 64 + mi * 16 + (lane >> 2);
        #pragma unroll
        for (int ni = 0; ni < 4; ni++) {
            int c = tileN + wn * 32 + ni * 8 + 2 * (lane & 3);
            const float* bp = (c < 1024) ? bias0 : (c < 2048) ? bias1 : bias2;
            float b0 = bp[c & 1023], b1 = bp[(c + 1) & 1023];
            float o00 = fmaxf(acc[mi][ni][0] + b0, 0.f);
            float o01 = fmaxf(acc[mi][ni][1] + b1, 0.f);
            float o10 = fmaxf(acc[mi][ni][2] + b0, 0.f);
            float o11 = fmaxf(acc[mi][ni][3] + b1, 0.f);
            if (HALF_OUT) {
                __half* Ch = (__half*)Cv;
                *reinterpret_cast<__half2*>(Ch + (size_t)r0 * cstride + c) =
                    __floats2half2_rn(o00, o01);
                *reinterpret_cast<__half2*>(Ch + (size_t)(r0 + 8) * cstride + c) =
                    __floats2half2_rn(o10, o11);
            } else {
                float* Cf = (float*)Cv;
                float2 v0; v0.x = o00; v0.y = o01;
                float2 v1; v1.x = o10; v1.y = o11;
                *reinterpret_cast<float2*>(Cf + (size_t)r0 * cstride + c) = v0;
                *reinterpret_cast<float2*>(Cf + (size_t)(r0 + 8) * cstride + c) = v1;
            }
        }
    }
}

// ---------------------------------------------------------------------------
// Prep kernels (fp16 rn conversion)
// ---------------------------------------------------------------------------
__global__ void __launch_bounds__(256) prep_a(
    const float* __restrict__ X, const float* __restrict__ STE,
    __half* __restrict__ A)
{
    size_t idx = (size_t)blockIdx.x * 256 + threadIdx.x;   // one float4
    size_t row = idx >> 9;
    int    c4  = (int)(idx & 511) * 4;
    const float4 v = (c4 < 1024)
        ? *reinterpret_cast<const float4*>(X + row * 1024 + c4)
        : *reinterpret_cast<const float4*>(STE + row * 1024 + (c4 - 1024));
    ushort4 o;
    o.x = __half_as_ushort(__float2half_rn(v.x));
    o.y = __half_as_ushort(__float2half_rn(v.y));
    o.z = __half_as_ushort(__float2half_rn(v.z));
    o.w = __half_as_ushort(__float2half_rn(v.w));
    *reinterpret_cast<ushort4*>(A + row * 2048 + c4) = o;
}

// W [K,1024] -> WT [1024,K] fp16; blockIdx.z selects (Wq,Wk,Wv)
__global__ void __launch_bounds__(256) prep_wt_qkv(
    const float* __restrict__ W0, const float* __restrict__ W1,
    const float* __restrict__ W2, __half* __restrict__ WT)
{
    __shared__ float t[32][33];
    const float* W = (blockIdx.z == 0) ? W0 : (blockIdx.z == 1) ? W1 : W2;
    __half* O = WT + (size_t)blockIdx.z * 1024 * K2;
    const int kb = blockIdx.x * 32, nb = blockIdx.y * 32;
    const int x = threadIdx.x, y = threadIdx.y;
    #pragma unroll
    for (int i = 0; i < 32; i += 8)
        t[y + i][x] = W[(size_t)(kb + y + i) * 1024 + nb + x];
    __syncthreads();
    #pragma unroll
    for (int i = 0; i < 32; i += 8)
        O[(size_t)(nb + y + i) * K2 + kb + x] = __float2half_rn(t[x][y + i]);
}

__global__ void __launch_bounds__(256) prep_wt_o(
    const float* __restrict__ W, __half* __restrict__ WT)
{
    __shared__ float t[32][33];
    const int kb = blockIdx.x * 32, nb = blockIdx.y * 32;
    const int x = threadIdx.x, y = threadIdx.y;
    #pragma unroll
    for (int i = 0; i < 32; i += 8)
        t[y + i][x] = W[(size_t)(kb + y + i) * 1024 + nb + x];
    __syncthreads();
    #pragma unroll
    for (int i = 0; i < 32; i += 8)
        WT[(size_t)(nb + y + i) * D_DIM + kb + x] = __float2half_rn(t[x][y + i]);
}

// ---------------------------------------------------------------------------
// Causal attention per (b, n, head); qkv fused [32768, 3072] fp16.
// 2x2 register-tiled scores, __expf softmax, 2-row-tiled AV.
// Output written fp16 (feeds Wo GEMM directly).
// ---------------------------------------------------------------------------
__global__ void __launch_bounds__(128) attn_kernel(
    const __half* __restrict__ QKV, __half* __restrict__ O)
{
    __shared__ float qs[64][33];
    __shared__ float ks[64][33];
    __shared__ float vs[64][33];
    __shared__ float ps[64][65];

    const int bid = blockIdx.x;
    const int h = bid & 31;
    const int n = (bid >> 5) & 127;
    const int b = bid >> 12;
    const int tid = threadIdx.x;
    const int lane = tid & 31;
    const int warp = tid >> 5;

    const int hc = h * 32 + lane;

    #pragma unroll
    for (int i = 0; i < 16; i++) {
        int t = warp * 16 + i;
        size_t row = ((size_t)b * 64 + t) * 128 + n;
        const __half* r = QKV + row * 3072;
        qs[t][lane] = __half2float(r[hc]);
        ks[t][lane] = __half2float(r[1024 + hc]);
        vs[t][lane] = __half2float(r[2048 + hc]);
    }
    __syncthreads();

    // ---- scores: warp handles t-pairs (t0, t0+1); K rows in registers ----
    float k0r[32], k1r[32];
    #pragma unroll
    for (int kk = 0; kk < 32; kk++) {
        k0r[kk] = ks[lane][kk];
        k1r[kk] = ks[lane + 32][kk];
    }
    const float scale = 0.17677669529663687f;  // 1/sqrt(32)
    #pragma unroll 1
    for (int j = 0; j < 8; j++) {
        const int t0 = 2 * warp + 8 * j;       // warp-uniform
        const int t1 = t0 + 1;
        float a00 = 0.f, a01 = 0.f, a10 = 0.f, a11 = 0.f;
        if (t1 >= 32) {
            #pragma unroll
            for (int kk = 0; kk < 32; kk++) {
                float q0 = qs[t0][kk], q1 = qs[t1][kk];
                a00 = fmaf(q0, k0r[kk], a00);
                a01 = fmaf(q0, k1r[kk], a01);
                a10 = fmaf(q1, k0r[kk], a10);
                a11 = fmaf(q1, k1r[kk], a11);
            }
        } else {
            #pragma unroll
            for (int kk = 0; kk < 32; kk++) {
                float q0 = qs[t0][kk], q1 = qs[t1][kk];
                a00 = fmaf(q0, k0r[kk], a00);
                a10 = fmaf(q1, k0r[kk], a10);
            }
        }
        if (lane <= t0)      ps[t0][lane]      = a00 * scale;
        if (lane <= t1)      ps[t1][lane]      = a10 * scale;
        if (lane + 32 <= t0) ps[t0][lane + 32] = a01 * scale;
        if (lane + 32 <= t1) ps[t1][lane + 32] = a11 * scale;
    }
    __syncthreads();

    // ---- softmax per row (masked entries written as exact 0) ----
    #pragma unroll 1
    for (int i = 0; i < 16; i++) {
        int t = warp * 16 + i;
        float x0 = (lane <= t) ? ps[t][lane] : -1e30f;
        float x1 = (lane + 32 <= t) ? ps[t][lane + 32] : -1e30f;
        float m = fmaxf(x0, x1);
        #pragma unroll
        for (int o = 16; o; o >>= 1) m = fmaxf(m, __shfl_xor_sync(0xffffffffu, m, o));
        float e0 = (lane <= t) ? __expf(x0 - m) : 0.f;
        float e1 = (lane + 32 <= t) ? __expf(x1 - m) : 0.f;
        float sum = e0 + e1;
        #pragma unroll
        for (int o = 16; o; o >>= 1) sum += __shfl_xor_sync(0xffffffffu, sum, o);
        float inv = 1.f / sum;
        ps[t][lane] = e0 * inv;
        ps[t][lane + 32] = e1 * inv;
    }
    __syncthreads();

    // ---- AV: t-pairs share vs loads; upper-triangle ps entries are 0 ----
    #pragma unroll 1
    for (int i = 0; i < 8; i++) {
        const int t0 = 2 * warp + 8 * i;
        const int t1 = t0 + 1;
        float acc0 = 0.f, acc1 = 0.f;
        for (int s = 0; s <= t1; s++) {
            float v = vs[s][lane];
            acc0 = fmaf(ps[t0][s], v, acc0);   // ps[t0][t1] == 0
            acc1 = fmaf(ps[t1][s], v, acc1);
        }
        size_t row0 = ((size_t)b * 64 + t0) * 128 + n;
        O[row0 * 1024 + hc] = __float2half_rn(acc0);
        O[(row0 + 128) * 1024 + hc] = __float2half_rn(acc1);
    }
}

// ---------------------------------------------------------------------------
extern "C" void kernel_launch(void* const* d_in, const int* in_sizes, int n_in,
                              void* d_out, int out_size)
{
    const float* X   = (const float*)d_in[0];
    const float* STE = (const float*)d_in[1];
    const float* Wq  = (const float*)d_in[2];
    const float* bq  = (const float*)d_in[3];
    const float* Wk  = (const float*)d_in[4];
    const float* bk  = (const float*)d_in[5];
    const float* Wv  = (const float*)d_in[6];
    const float* bv  = (const float*)d_in[7];
    const float* Wo  = (const float*)d_in[8];
    const float* bo  = (const float*)d_in[9];
    float* out = (float*)d_out;

    unsigned char* sc = nullptr;
    cudaGetSymbolAddress((void**)&sc, g_scratch);
    __half* qkv = (__half*)(sc + OFF_QKV);
    __half* A   = (__half*)(sc + OFF_A);
    __half* AOR = (__half*)(sc + OFF_AOR);
    __half* WT  = (__half*)(sc + OFF_WT);
    __half* WOT = (__half*)(sc + OFF_WOT);

    cudaFuncSetAttribute(mma_gemm<1>,
                         cudaFuncAttributeMaxDynamicSharedMemorySize,
                         GEMM_SMEM);
    cudaFuncSetAttribute(mma_gemm<0>,
                         cudaFuncAttributeMaxDynamicSharedMemorySize,
                         GEMM_SMEM);

    dim3 tb(32, 8);
    prep_a<<<65536, 256>>>(X, STE, A);                        // launch 0
    prep_wt_qkv<<<dim3(64, 32, 3), tb>>>(Wq, Wk, Wv, WT);     // launch 1
    prep_wt_o<<<dim3(32, 32), tb>>>(Wo, WOT);                 // launch 2

    // launch 3 (profiled): fused QKV projection -> fp16 qkv
    mma_gemm<1><<<dim3(NEFF / 128, M_TOTAL / 128), 256, GEMM_SMEM>>>(
        A, WT, bq, bk, bv, qkv, K2, NEFF);

    // causal temporal attention (fp16 in/out)
    attn_kernel<<<B_SZ * N_SZ * 32, 128>>>(qkv, AOR);

    // output projection -> fp32 out
    mma_gemm<0><<<dim3(D_DIM / 128, M_TOTAL / 128), 256, GEMM_SMEM>>>(
        AOR, WOT, bo, bo, bo, out, D_DIM, D_DIM);
}

// round 16
// speedup vs baseline: 2.3945x; 1.1464x over previous
#include <cuda_runtime.h>
#include <cuda_fp16.h>
#include <math.h>
#include <stdint.h>

// ---------------------------------------------------------------------------
// Problem constants
// ---------------------------------------------------------------------------
#define B_SZ 4
#define T_SZ 64
#define N_SZ 128
#define D_DIM 1024
#define K2 2048
#define M_TOTAL 32768              // B*T*N
#define NEFF 3072                  // fused QKV output cols

// ---------------------------------------------------------------------------
// Scratch carve-out (single __device__ blob; allocation-free rule)
// ---------------------------------------------------------------------------
#define OFF_QKV  ((size_t)0)                        // fp16 [32768,3072]
#define OFF_A    (OFF_QKV + (size_t)201326592)      // fp16 [32768,2048]
#define OFF_AOR  (OFF_A   + (size_t)134217728)      // fp16 [32768,1024]
#define OFF_WT   (OFF_AOR + (size_t)67108864)       // fp16 [3072,2048]
#define OFF_WOT  (OFF_WT  + (size_t)12582912)       // fp16 [1024,1024]
#define SCRATCH_BYTES (OFF_WOT + (size_t)2097152)

__device__ __align__(1024) unsigned char g_scratch[SCRATCH_BYTES];

// ---------------------------------------------------------------------------
// PTX helpers (base sm_100 features only; mbarrier is sm_80+)
// ---------------------------------------------------------------------------
static __device__ __forceinline__ unsigned smem_u32(const void* p) {
    unsigned r;
    asm("{ .reg .u64 t; cvta.to.shared.u64 t, %1; cvt.u32.u64 %0, t; }"
        : "=r"(r) : "l"(p));
    return r;
}
static __device__ __forceinline__ void cp16(unsigned dst, const void* src) {
    asm volatile("cp.async.cg.shared.global [%0], [%1], 16;"
                 :: "r"(dst), "l"(src) : "memory");
}
static __device__ __forceinline__ void mbar_init(unsigned a, unsigned cnt) {
    asm volatile("mbarrier.init.shared.b64 [%0], %1;" :: "r"(a), "r"(cnt) : "memory");
}
static __device__ __forceinline__ void mbar_arrive(unsigned a) {
    asm volatile("mbarrier.arrive.shared.b64 _, [%0];"
                 :: "r"(a) : "memory");
}
// deferred arrive: fires on this thread's prior cp.async completion
static __device__ __forceinline__ void cp_arrive(unsigned a) {
    asm volatile("cp.async.mbarrier.arrive.noinc.shared.b64 [%0];"
                 :: "r"(a) : "memory");
}
static __device__ __forceinline__ void mbar_wait(unsigned a, unsigned parity) {
    asm volatile(
        "{\n\t.reg .pred P;\n\t"
        "W%=:\n\t"
        "mbarrier.try_wait.parity.acquire.cta.shared::cta.b64 P, [%0], %1, 0x989680;\n\t"
        "@P bra D%=;\n\t"
        "bra W%=;\n\t"
        "D%=:\n\t}"
        :: "r"(a), "r"(parity) : "memory");
}
static __device__ __forceinline__ void ldmx4(
    unsigned& r0, unsigned& r1, unsigned& r2, unsigned& r3, unsigned addr) {
    asm volatile("ldmatrix.sync.aligned.m8n8.x4.shared.b16 {%0,%1,%2,%3}, [%4];"
                 : "=r"(r0), "=r"(r1), "=r"(r2), "=r"(r3) : "r"(addr));
}
static __device__ __forceinline__ void mma_f16(
    float* c, const unsigned* a, unsigned b0, unsigned b1) {
    asm volatile(
        "mma.sync.aligned.m16n8k16.row.col.f32.f16.f16.f32 "
        "{%0,%1,%2,%3}, {%4,%5,%6,%7}, {%8,%9}, {%0,%1,%2,%3};"
        : "+f"(c[0]), "+f"(c[1]), "+f"(c[2]), "+f"(c[3])
        : "r"(a[0]), "r"(a[1]), "r"(a[2]), "r"(a[3]), "r"(b0), "r"(b1));
}

// ---------------------------------------------------------------------------
// fp16 GEMM via mma.sync.m16n8k16 with an mbarrier producer/consumer pipe:
// NO __syncthreads / wait_group in the mainloop — warps drift independently
// (bounded by 3 stages), decorrelating LDSM-head / boundary stalls.
// CTA tile 128x128, BK=64, 8 warps (warptile 64x32), 3 stages, 2 CTAs/SM.
// ---------------------------------------------------------------------------
#define PADK 72                        // halves per padded smem row (144B)
#define A_ST (128 * PADK * 2)          // 18432 B
#define B_ST (128 * PADK * 2)          // 18432 B
#define ST_BYTES (A_ST + B_ST)         // 36864 B
#define NSTG 3
#define GEMM_SMEM (NSTG * ST_BYTES)    // 110592 B per CTA

template <int HALF_OUT>
__global__ void __launch_bounds__(256, 2) mma_gemm(
    const __half* __restrict__ A,
    const __half* __restrict__ WT,
    const float* __restrict__ bias0,   // cols [0,1024)
    const float* __restrict__ bias1,   // cols [1024,2048)
    const float* __restrict__ bias2,   // cols [2048,3072)
    void* __restrict__ Cv,
    int K, int cstride)
{
    extern __shared__ __align__(16) unsigned char smem[];
    __shared__ __align__(8) unsigned long long mbF[NSTG], mbE[NSTG];
    const unsigned sbase = smem_u32(smem);

    const int tid  = threadIdx.x;
    const int lane = tid & 31;
    const int warp = tid >> 5;
    const int wm   = warp >> 2;          // 0..1 (64-row slab)
    const int wn   = warp & 3;           // 0..3 (32-col slab)
    const int tileM = blockIdx.y * 128;
    const int tileN = blockIdx.x * 128;

    const int NC = K >> 6;               // 64-wide K chunks (>= 16)

    if (tid == 0) {
        #pragma unroll
        for (int s = 0; s < NSTG; s++) {
            mbar_init(smem_u32(&mbF[s]), 256);   // full: 256 deferred cp-arrives
            mbar_init(smem_u32(&mbE[s]), 256);   // empty: 256 consumer arrives
        }
    }
    __syncthreads();                     // mbarrier init visibility (only sync)

    float acc[4][4][4];
    #pragma unroll
    for (int mi = 0; mi < 4; mi++)
        #pragma unroll
        for (int ni = 0; ni < 4; ni++)
            #pragma unroll
            for (int e = 0; e < 4; e++) acc[mi][ni][e] = 0.f;

    // copy chunk kc into stage s. A,B each 128x64 fp16 (128B/row): 4 cp16/thread
    auto do_copy = [&](int kc, int s) {
        const int klocal = kc << 6;
        const unsigned stA = sbase + s * ST_BYTES;
        const unsigned stB = stA + A_ST;
        #pragma unroll
        for (int i = 0; i < 4; i++) {
            int idx = tid + i * 256;          // 0..1023
            int r = idx >> 3, c = idx & 7;    // c: 16B segment (8 halves)
            cp16(stA + r * (PADK * 2) + c * 16,
                 A + (size_t)(tileM + r) * K + klocal + c * 8);
        }
        #pragma unroll
        for (int i = 0; i < 4; i++) {
            int idx = tid + i * 256;
            int r = idx >> 3, c = idx & 7;
            cp16(stB + r * (PADK * 2) + c * 16,
                 WT + (size_t)(tileN + r) * K + klocal + c * 8);
        }
    };

    // prologue: chunks 0,1 -> stages 0,1 (deferred full-arrives)
    do_copy(0, 0); cp_arrive(smem_u32(&mbF[0]));
    do_copy(1, 1); cp_arrive(smem_u32(&mbF[1]));

    int s = 0, pf = 0;                   // consumer cursor: stage, full-parity
    int sp = 2, pe = 1;                  // producer cursor: stage, empty-parity
    for (int kc = 0; kc < NC; kc++) {
        mbar_wait(smem_u32(&mbF[s]), pf);      // chunk kc resident

        const unsigned stA = sbase + s * ST_BYTES;
        const unsigned stB = stA + A_ST;
        #pragma unroll
        for (int ks = 0; ks < 4; ks++) {       // four k16 steps per 64-chunk
            unsigned a[4][4];
            #pragma unroll
            for (int mi = 0; mi < 4; mi++) {
                int row = wm * 64 + mi * 16 + (lane & 15);
                int kb  = ks * 16 + (lane >> 4) * 8;
                ldmx4(a[mi][0], a[mi][1], a[mi][2], a[mi][3],
                      stA + row * (PADK * 2) + kb * 2);
            }
            unsigned b[4][2];
            #pragma unroll
            for (int ng = 0; ng < 2; ng++) {
                int row = wn * 32 + ng * 16 + ((lane >> 4) << 3) + (lane & 7);
                int kb  = ks * 16 + ((lane >> 3) & 1) * 8;
                unsigned r0, r1, r2, r3;
                ldmx4(r0, r1, r2, r3, stB + row * (PADK * 2) + kb * 2);
                b[ng * 2][0] = r0;      b[ng * 2][1] = r1;
                b[ng * 2 + 1][0] = r2;  b[ng * 2 + 1][1] = r3;
            }
            #pragma unroll
            for (int mi = 0; mi < 4; mi++)
                #pragma unroll
                for (int ni = 0; ni < 4; ni++)
                    mma_f16(acc[mi][ni], a[mi], b[ni][0], b[ni][1]);
        }

        mbar_arrive(smem_u32(&mbE[s]));        // done reading stage s

        // produce chunk kc+2 into stage sp (WAR-guarded by empty barrier)
        const int kn = kc + 2;
        if (kn < NC) {
            if (kn >= NSTG) mbar_wait(smem_u32(&mbE[sp]), pe);
            do_copy(kn, sp);
            cp_arrive(smem_u32(&mbF[sp]));
        }
        if (++s == NSTG) { s = 0; pf ^= 1; }
        if (++sp == NSTG) { sp = 0; pe ^= 1; }
    }

    // epilogue: bias + relu; fp16 or fp32 output (warp-private tiles, no sync)
    #pragma unroll
    for (int mi = 0; mi < 4; mi++) {
        int r0 = tileM + wm * 64 + mi * 16 + (lane >> 2);
        #pragma unroll
        for (int ni = 0; ni < 4; ni++) {
            int c = tileN + wn * 32 + ni * 8 + 2 * (lane & 3);
            const float* bp = (c < 1024) ? bias0 : (c < 2048) ? bias1 : bias2;
            float b0 = bp[c & 1023], b1 = bp[(c + 1) & 1023];
            float o00 = fmaxf(acc[mi][ni][0] + b0, 0.f);
            float o01 = fmaxf(acc[mi][ni][1] + b1, 0.f);
            float o10 = fmaxf(acc[mi][ni][2] + b0, 0.f);
            float o11 = fmaxf(acc[mi][ni][3] + b1, 0.f);
            if (HALF_OUT) {
                __half* Ch = (__half*)Cv;
                *reinterpret_cast<__half2*>(Ch + (size_t)r0 * cstride + c) =
                    __floats2half2_rn(o00, o01);
                *reinterpret_cast<__half2*>(Ch + (size_t)(r0 + 8) * cstride + c) =
                    __floats2half2_rn(o10, o11);
            } else {
                float* Cf = (float*)Cv;
                float2 v0; v0.x = o00; v0.y = o01;
                float2 v1; v1.x = o10; v1.y = o11;
                *reinterpret_cast<float2*>(Cf + (size_t)r0 * cstride + c) = v0;
                *reinterpret_cast<float2*>(Cf + (size_t)(r0 + 8) * cstride + c) = v1;
            }
        }
    }
}

// ---------------------------------------------------------------------------
// Prep kernels (fp16 rn conversion)
// ---------------------------------------------------------------------------
__global__ void __launch_bounds__(256) prep_a(
    const float* __restrict__ X, const float* __restrict__ STE,
    __half* __restrict__ A)
{
    size_t idx = (size_t)blockIdx.x * 256 + threadIdx.x;   // one float4
    size_t row = idx >> 9;
    int    c4  = (int)(idx & 511) * 4;
    const float4 v = (c4 < 1024)
        ? *reinterpret_cast<const float4*>(X + row * 1024 + c4)
        : *reinterpret_cast<const float4*>(STE + row * 1024 + (c4 - 1024));
    ushort4 o;
    o.x = __half_as_ushort(__float2half_rn(v.x));
    o.y = __half_as_ushort(__float2half_rn(v.y));
    o.z = __half_as_ushort(__float2half_rn(v.z));
    o.w = __half_as_ushort(__float2half_rn(v.w));
    *reinterpret_cast<ushort4*>(A + row * 2048 + c4) = o;
}

// W [K,1024] -> WT [1024,K] fp16; blockIdx.z selects (Wq,Wk,Wv)
__global__ void __launch_bounds__(256) prep_wt_qkv(
    const float* __restrict__ W0, const float* __restrict__ W1,
    const float* __restrict__ W2, __half* __restrict__ WT)
{
    __shared__ float t[32][33];
    const float* W = (blockIdx.z == 0) ? W0 : (blockIdx.z == 1) ? W1 : W2;
    __half* O = WT + (size_t)blockIdx.z * 1024 * K2;
    const int kb = blockIdx.x * 32, nb = blockIdx.y * 32;
    const int x = threadIdx.x, y = threadIdx.y;
    #pragma unroll
    for (int i = 0; i < 32; i += 8)
        t[y + i][x] = W[(size_t)(kb + y + i) * 1024 + nb + x];
    __syncthreads();
    #pragma unroll
    for (int i = 0; i < 32; i += 8)
        O[(size_t)(nb + y + i) * K2 + kb + x] = __float2half_rn(t[x][y + i]);
}

__global__ void __launch_bounds__(256) prep_wt_o(
    const float* __restrict__ W, __half* __restrict__ WT)
{
    __shared__ float t[32][33];
    const int kb = blockIdx.x * 32, nb = blockIdx.y * 32;
    const int x = threadIdx.x, y = threadIdx.y;
    #pragma unroll
    for (int i = 0; i < 32; i += 8)
        t[y + i][x] = W[(size_t)(kb + y + i) * 1024 + nb + x];
    __syncthreads();
    #pragma unroll
    for (int i = 0; i < 32; i += 8)
        WT[(size_t)(nb + y + i) * D_DIM + kb + x] = __float2half_rn(t[x][y + i]);
}

// ---------------------------------------------------------------------------
// Causal attention per (b, n, head); qkv fused [32768, 3072] fp16.
// 2x2 register-tiled scores, __expf softmax, 2-row-tiled AV.
// Output written fp16 (feeds Wo GEMM directly).
// ---------------------------------------------------------------------------
__global__ void __launch_bounds__(128) attn_kernel(
    const __half* __restrict__ QKV, __half* __restrict__ O)
{
    __shared__ float qs[64][33];
    __shared__ float ks[64][33];
    __shared__ float vs[64][33];
    __shared__ float ps[64][65];

    const int bid = blockIdx.x;
    const int h = bid & 31;
    const int n = (bid >> 5) & 127;
    const int b = bid >> 12;
    const int tid = threadIdx.x;
    const int lane = tid & 31;
    const int warp = tid >> 5;

    const int hc = h * 32 + lane;

    #pragma unroll
    for (int i = 0; i < 16; i++) {
        int t = warp * 16 + i;
        size_t row = ((size_t)b * 64 + t) * 128 + n;
        const __half* r = QKV + row * 3072;
        qs[t][lane] = __half2float(r[hc]);
        ks[t][lane] = __half2float(r[1024 + hc]);
        vs[t][lane] = __half2float(r[2048 + hc]);
    }
    __syncthreads();

    // ---- scores: warp handles t-pairs (t0, t0+1); K rows in registers ----
    float k0r[32], k1r[32];
    #pragma unroll
    for (int kk = 0; kk < 32; kk++) {
        k0r[kk] = ks[lane][kk];
        k1r[kk] = ks[lane + 32][kk];
    }
    const float scale = 0.17677669529663687f;  // 1/sqrt(32)
    #pragma unroll 1
    for (int j = 0; j < 8; j++) {
        const int t0 = 2 * warp + 8 * j;       // warp-uniform
        const int t1 = t0 + 1;
        float a00 = 0.f, a01 = 0.f, a10 = 0.f, a11 = 0.f;
        if (t1 >= 32) {
            #pragma unroll
            for (int kk = 0; kk < 32; kk++) {
                float q0 = qs[t0][kk], q1 = qs[t1][kk];
                a00 = fmaf(q0, k0r[kk], a00);
                a01 = fmaf(q0, k1r[kk], a01);
                a10 = fmaf(q1, k0r[kk], a10);
                a11 = fmaf(q1, k1r[kk], a11);
            }
        } else {
            #pragma unroll
            for (int kk = 0; kk < 32; kk++) {
                float q0 = qs[t0][kk], q1 = qs[t1][kk];
                a00 = fmaf(q0, k0r[kk], a00);
                a10 = fmaf(q1, k0r[kk], a10);
            }
        }
        if (lane <= t0)      ps[t0][lane]      = a00 * scale;
        if (lane <= t1)      ps[t1][lane]      = a10 * scale;
        if (lane + 32 <= t0) ps[t0][lane + 32] = a01 * scale;
        if (lane + 32 <= t1) ps[t1][lane + 32] = a11 * scale;
    }
    __syncthreads();

    // ---- softmax per row (masked entries written as exact 0) ----
    #pragma unroll 1
    for (int i = 0; i < 16; i++) {
        int t = warp * 16 + i;
        float x0 = (lane <= t) ? ps[t][lane] : -1e30f;
        float x1 = (lane + 32 <= t) ? ps[t][lane + 32] : -1e30f;
        float m = fmaxf(x0, x1);
        #pragma unroll
        for (int o = 16; o; o >>= 1) m = fmaxf(m, __shfl_xor_sync(0xffffffffu, m, o));
        float e0 = (lane <= t) ? __expf(x0 - m) : 0.f;
        float e1 = (lane + 32 <= t) ? __expf(x1 - m) : 0.f;
        float sum = e0 + e1;
        #pragma unroll
        for (int o = 16; o; o >>= 1) sum += __shfl_xor_sync(0xffffffffu, sum, o);
        float inv = 1.f / sum;
        ps[t][lane] = e0 * inv;
        ps[t][lane + 32] = e1 * inv;
    }
    __syncthreads();

    // ---- AV: t-pairs share vs loads; upper-triangle ps entries are 0 ----
    #pragma unroll 1
    for (int i = 0; i < 8; i++) {
        const int t0 = 2 * warp + 8 * i;
        const int t1 = t0 + 1;
        float acc0 = 0.f, acc1 = 0.f;
        for (int s = 0; s <= t1; s++) {
            float v = vs[s][lane];
            acc0 = fmaf(ps[t0][s], v, acc0);   // ps[t0][t1] == 0
            acc1 = fmaf(ps[t1][s], v, acc1);
        }
        size_t row0 = ((size_t)b * 64 + t0) * 128 + n;
        O[row0 * 1024 + hc] = __float2half_rn(acc0);
        O[(row0 + 128) * 1024 + hc] = __float2half_rn(acc1);
    }
}

// ---------------------------------------------------------------------------
extern "C" void kernel_launch(void* const* d_in, const int* in_sizes, int n_in,
                              void* d_out, int out_size)
{
    const float* X   = (const float*)d_in[0];
    const float* STE = (const float*)d_in[1];
    const float* Wq  = (const float*)d_in[2];
    const float* bq  = (const float*)d_in[3];
    const float* Wk  = (const float*)d_in[4];
    const float* bk  = (const float*)d_in[5];
    const float* Wv  = (const float*)d_in[6];
    const float* bv  = (const float*)d_in[7];
    const float* Wo  = (const float*)d_in[8];
    const float* bo  = (const float*)d_in[9];
    float* out = (float*)d_out;

    unsigned char* sc = nullptr;
    cudaGetSymbolAddress((void**)&sc, g_scratch);
    __half* qkv = (__half*)(sc + OFF_QKV);
    __half* A   = (__half*)(sc + OFF_A);
    __half* AOR = (__half*)(sc + OFF_AOR);
    __half* WT  = (__half*)(sc + OFF_WT);
    __half* WOT = (__half*)(sc + OFF_WOT);

    cudaFuncSetAttribute(mma_gemm<1>,
                         cudaFuncAttributeMaxDynamicSharedMemorySize,
                         GEMM_SMEM);
    cudaFuncSetAttribute(mma_gemm<0>,
                         cudaFuncAttributeMaxDynamicSharedMemorySize,
                         GEMM_SMEM);

    dim3 tb(32, 8);
    prep_a<<<65536, 256>>>(X, STE, A);                        // launch 0
    prep_wt_qkv<<<dim3(64, 32, 3), tb>>>(Wq, Wk, Wv, WT);     // launch 1
    prep_wt_o<<<dim3(32, 32), tb>>>(Wo, WOT);                 // launch 2

    // launch 3 (profiled): fused QKV projection -> fp16 qkv
    mma_gemm<1><<<dim3(NEFF / 128, M_TOTAL / 128), 256, GEMM_SMEM>>>(
        A, WT, bq, bk, bv, qkv, K2, NEFF);

    // causal temporal attention (fp16 in/out)
    attn_kernel<<<B_SZ * N_SZ * 32, 128>>>(qkv, AOR);

    // output projection -> fp32 out
    mma_gemm<0><<<dim3(D_DIM / 128, M_TOTAL / 128), 256, GEMM_SMEM>>>(
        AOR, WOT, bo, bo, bo, out, D_DIM, D_DIM);
}